// round 2
// baseline (speedup 1.0000x reference)
#include <cuda_runtime.h>
#include <math.h>

// ---------------- problem constants ----------------
#define NTOK   4096          // N*T = 2*2048
#define TSEQ   2048
#define DM     1024          // d_model
#define DIP    4384          // d_in_proj
#define DINNER 2048
#define CONVD  2304          // d_inner + 2*d_state
#define HS     32            // ssm heads
#define PD     64            // headdim
#define DS     128           // d_state
#define CH     256           // chunk
#define NC     8             // chunks per sequence

// ---------------- scratch layout (floats) ----------------
#define OFF_Q    0ull                 // 4096*1024   roped q (residual)
#define OFF_H    4194304ull           // 4096*1024   rmsnormed h
#define OFF_ZX   8388608ull           // 4096*4384   zxbcdt
#define OFF_XBC  26345472ull          // 4096*2304   conv+silu output
#define OFF_DT   35782656ull          // 4096*32     softplus dt
#define OFF_G    35913728ull          // 16*256*256  G^T per (b,c): [s][l]
#define OFF_ST   36962304ull          // 16*32*64*128 chunk states -> states_prev
#define OFF_ASUM 41156608ull          // 2*32*8      chunk A sums
#define OFF_EACS 41157120ull          // 16*32*256   exp(Acs)
#define OFF_Y    41288192ull          // 4096*2048   y
#define OFF_YG   49676800ull          // 4096*2048   gated normed y
#define SCRATCH_FLOATS 58065408ull

__device__ float g_scratch[SCRATCH_FLOATS];

// ---------------- helpers ----------------
__device__ __forceinline__ float block_sum256(float v, float* red) {
    #pragma unroll
    for (int o = 16; o; o >>= 1) v += __shfl_down_sync(0xffffffffu, v, o);
    int lane = threadIdx.x & 31, wid = threadIdx.x >> 5;
    if (lane == 0) red[wid] = v;
    __syncthreads();
    if (wid == 0) {
        float w = (lane < 8) ? red[lane] : 0.f;
        #pragma unroll
        for (int o = 16; o; o >>= 1) w += __shfl_down_sync(0xffffffffu, w, o);
        if (lane == 0) red[0] = w;
    }
    __syncthreads();
    return red[0];
}

// ---------------- generic tiled fp32 GEMM: C = A(MxK) * B(NxK)^T (+ addC) ----------------
// 64x64 tile, BK=16, 256 threads, 4x4 per thread. Optionally batched (blockIdx.z).
__global__ void __launch_bounds__(256)
gemm_nt(const float* __restrict__ A, const float* __restrict__ B,
        float* __restrict__ C, const float* __restrict__ addC,
        int M, int N, int K, int lda, int ldb, int ldc,
        size_t bsA, size_t bsB, size_t bsC)
{
    A += bsA * blockIdx.z;
    B += bsB * blockIdx.z;
    C += bsC * blockIdx.z;

    __shared__ float As[16][64];
    __shared__ float Bs[16][64];

    int m0 = blockIdx.y * 64, n0 = blockIdx.x * 64;
    int tid = threadIdx.x;
    int tx = tid & 15, ty = tid >> 4;
    int lr = tid >> 2;          // 0..63 row in tile
    int lc = (tid & 3) << 2;    // 0,4,8,12 k offset

    float acc[4][4];
    #pragma unroll
    for (int i = 0; i < 4; i++)
        #pragma unroll
        for (int j = 0; j < 4; j++) acc[i][j] = 0.f;

    for (int k0 = 0; k0 < K; k0 += 16) {
        float4 av = make_float4(0.f, 0.f, 0.f, 0.f);
        float4 bv = make_float4(0.f, 0.f, 0.f, 0.f);
        if (m0 + lr < M) av = *(const float4*)(A + (size_t)(m0 + lr) * lda + k0 + lc);
        if (n0 + lr < N) bv = *(const float4*)(B + (size_t)(n0 + lr) * ldb + k0 + lc);
        As[lc + 0][lr] = av.x; As[lc + 1][lr] = av.y; As[lc + 2][lr] = av.z; As[lc + 3][lr] = av.w;
        Bs[lc + 0][lr] = bv.x; Bs[lc + 1][lr] = bv.y; Bs[lc + 2][lr] = bv.z; Bs[lc + 3][lr] = bv.w;
        __syncthreads();
        #pragma unroll
        for (int kk = 0; kk < 16; kk++) {
            float4 a  = *(const float4*)(&As[kk][ty << 2]);
            float4 bq = *(const float4*)(&Bs[kk][tx << 2]);
            acc[0][0] += a.x * bq.x; acc[0][1] += a.x * bq.y; acc[0][2] += a.x * bq.z; acc[0][3] += a.x * bq.w;
            acc[1][0] += a.y * bq.x; acc[1][1] += a.y * bq.y; acc[1][2] += a.y * bq.z; acc[1][3] += a.y * bq.w;
            acc[2][0] += a.z * bq.x; acc[2][1] += a.z * bq.y; acc[2][2] += a.z * bq.z; acc[2][3] += a.z * bq.w;
            acc[3][0] += a.w * bq.x; acc[3][1] += a.w * bq.y; acc[3][2] += a.w * bq.z; acc[3][3] += a.w * bq.w;
        }
        __syncthreads();
    }

    #pragma unroll
    for (int i = 0; i < 4; i++) {
        int m = m0 + (ty << 2) + i;
        if (m >= M) continue;
        #pragma unroll
        for (int j = 0; j < 4; j++) {
            int n = n0 + (tx << 2) + j;
            if (n >= N) continue;
            float v = acc[i][j];
            if (addC) v += addC[(size_t)m * ldc + n];
            C[(size_t)m * ldc + n] = v;
        }
    }
}

// ---------------- rope (in place) + rmsnorm into h ----------------
__global__ void __launch_bounds__(256)
rope_norm_kernel(float* __restrict__ q, float* __restrict__ h,
                 const float* __restrict__ w)
{
    int tok = blockIdx.x;
    int t = tok & (TSEQ - 1);
    __shared__ float row[DM];
    __shared__ float red[8];
    int tid = threadIdx.x;
    for (int i = tid; i < DM; i += 256) row[i] = q[(size_t)tok * DM + i];
    __syncthreads();

    float vals[4];
    float ss = 0.f;
    #pragma unroll
    for (int u = 0; u < 4; u++) {
        int d  = tid + u * 256;
        int hd = d & 63;
        int i  = hd & 31;
        // inv_freq = 10000^(-(2i)/64)
        float inv = exp2f(-(float)(2 * i) * (1.f / 64.f) * 13.287712379549449f);
        float ang = (float)t * inv;
        float c, s;
        sincosf(ang, &s, &c);
        float v;
        if (hd < 32) { float q1 = row[d], q2 = row[d + 32]; v = q1 * c - q2 * s; }
        else         { float q2 = row[d], q1 = row[d - 32]; v = q2 * c + q1 * s; }
        vals[u] = v;
        ss += v * v;
    }
    float total = block_sum256(ss, red);
    float scale = rsqrtf(total * (1.f / DM) + 1e-5f);
    #pragma unroll
    for (int u = 0; u < 4; u++) {
        int d = tid + u * 256;
        q[(size_t)tok * DM + d] = vals[u];
        h[(size_t)tok * DM + d] = vals[u] * scale * w[d];
    }
}

// ---------------- dt = softplus(raw + bias) ----------------
__global__ void __launch_bounds__(256)
dt_kernel(const float* __restrict__ zx, const float* __restrict__ dtb,
          float* __restrict__ dt)
{
    int idx = blockIdx.x * blockDim.x + threadIdx.x;
    if (idx >= NTOK * HS) return;
    int tok = idx >> 5, hh = idx & 31;
    float x = zx[(size_t)tok * DIP + (DIP - HS) + hh] + dtb[hh];
    float sp = (x > 20.f) ? x : log1pf(expf(x));
    dt[idx] = sp;
}

// ---------------- causal depthwise conv (K=4) + silu ----------------
__global__ void __launch_bounds__(256)
conv_kernel(const float* __restrict__ zx, const float* __restrict__ cw,
            const float* __restrict__ cb, float* __restrict__ out)
{
    int idx = blockIdx.x * blockDim.x + threadIdx.x;
    if (idx >= NTOK * CONVD) return;
    int tok = idx / CONVD, ch = idx % CONVD;
    int t = tok & (TSEQ - 1);
    float acc = cb[ch];
    #pragma unroll
    for (int k = 0; k < 4; k++) {
        int tt = t + k - 3;
        if (tt >= 0) acc += zx[(size_t)(tok + k - 3) * DIP + DINNER + ch] * cw[ch * 4 + k];
    }
    float sg = 1.f / (1.f + expf(-acc));
    out[(size_t)tok * CONVD + ch] = acc * sg;
}

// ---------------- SSD part1: per (b,c,h) Y_diag + chunk states ----------------
__global__ void __launch_bounds__(256)
ssd_part1(const float* __restrict__ xBC, const float* __restrict__ dt,
          const float* __restrict__ A_log, const float* __restrict__ G,
          float* __restrict__ y, float* __restrict__ states,
          float* __restrict__ Asum, float* __restrict__ expAcs)
{
    int h = blockIdx.x, c = blockIdx.y, b = blockIdx.z;
    int l = threadIdx.x;
    int tok0 = b * TSEQ + c * CH;

    __shared__ float sAcs[CH];
    __shared__ float sDt[CH];
    __shared__ float sDec[CH];
    __shared__ float sES[64];
    __shared__ float sX[64][64];
    __shared__ float warpsum[8];

    float dtl = dt[(size_t)(tok0 + l) * HS + h];
    float A   = -expf(A_log[h]);
    float adt = dtl * A;

    // inclusive scan of adt over 256 threads
    int lane = l & 31, wid = l >> 5;
    float v = adt;
    #pragma unroll
    for (int o = 1; o < 32; o <<= 1) {
        float u = __shfl_up_sync(0xffffffffu, v, o);
        if (lane >= o) v += u;
    }
    if (lane == 31) warpsum[wid] = v;
    __syncthreads();
    if (wid == 0) {
        float w = (lane < 8) ? warpsum[lane] : 0.f;
        #pragma unroll
        for (int o = 1; o < 8; o <<= 1) {
            float u = __shfl_up_sync(0xffffffffu, w, o);
            if (lane >= o) w += u;
        }
        if (lane < 8) warpsum[lane] = w;
    }
    __syncthreads();
    float acs   = v + ((wid > 0) ? warpsum[wid - 1] : 0.f);
    float total = warpsum[7];

    sAcs[l] = acs;
    sDt[l]  = dtl;
    sDec[l] = expf(total - acs);
    expAcs[(((size_t)(b * NC + c) * HS) + h) * CH + l] = expf(acs);
    if (l == 0) Asum[(b * HS + h) * NC + c] = total;
    __syncthreads();

    const float* Gp = G + ((size_t)(b * NC + c)) * CH * CH;   // Gp[s*256 + l]

    float acc[64];
    #pragma unroll
    for (int p = 0; p < 64; p++) acc[p] = 0.f;

    for (int t4 = 0; t4 < 4; t4++) {
        int sbase = t4 * 64;
        __syncthreads();
        // stage xdt tile [64 rows s][64 cols p]
        for (int i = l; i < 64 * 64; i += 256) {
            int r = i >> 6, cc2 = i & 63;
            sX[r][cc2] = xBC[(size_t)(tok0 + sbase + r) * CONVD + h * PD + cc2] * sDt[sbase + r];
        }
        if (l < 64) sES[l] = expf(sAcs[sbase + 63] - sAcs[sbase + l]);
        __syncthreads();

        if (sbase + 63 < l) {
            // tile strictly below: both exp factors <= 1
            float f = expf(sAcs[l] - sAcs[sbase + 63]);
            for (int s = 0; s < 64; s++) {
                float w = Gp[(size_t)(sbase + s) * CH + l] * (f * sES[s]);
                const float4* xr = (const float4*)sX[s];
                #pragma unroll
                for (int p4 = 0; p4 < 16; p4++) {
                    float4 xx = xr[p4];
                    acc[p4 * 4 + 0] += w * xx.x;
                    acc[p4 * 4 + 1] += w * xx.y;
                    acc[p4 * 4 + 2] += w * xx.z;
                    acc[p4 * 4 + 3] += w * xx.w;
                }
            }
        } else if (sbase <= l) {
            // diagonal tile: per-element exp (<= 32 per thread on average)
            for (int s = sbase; s <= l; s++) {
                float w = Gp[(size_t)s * CH + l] * expf(sAcs[l] - sAcs[s]);
                const float4* xr = (const float4*)sX[s - sbase];
                #pragma unroll
                for (int p4 = 0; p4 < 16; p4++) {
                    float4 xx = xr[p4];
                    acc[p4 * 4 + 0] += w * xx.x;
                    acc[p4 * 4 + 1] += w * xx.y;
                    acc[p4 * 4 + 2] += w * xx.z;
                    acc[p4 * 4 + 3] += w * xx.w;
                }
            }
        }
    }

    // write Y_diag
    #pragma unroll
    for (int p = 0; p < 64; p++)
        y[(size_t)(tok0 + l) * DINNER + h * PD + p] = acc[p];
    __syncthreads();

    // chunk states: states[p][n] = sum_l B[l,n] * dec[l] * xdt[l,p]
    {
        int p  = l >> 2;
        int n0 = (l & 3) * 32;
        float st[32];
        #pragma unroll
        for (int i = 0; i < 32; i++) st[i] = 0.f;
        for (int ll = 0; ll < CH; ll++) {
            float coef = sDec[ll] * sDt[ll] * xBC[(size_t)(tok0 + ll) * CONVD + h * PD + p];
            const float4* bp = (const float4*)(xBC + (size_t)(tok0 + ll) * CONVD + DINNER + n0);
            #pragma unroll
            for (int j = 0; j < 8; j++) {
                float4 bb = bp[j];
                st[j * 4 + 0] += coef * bb.x;
                st[j * 4 + 1] += coef * bb.y;
                st[j * 4 + 2] += coef * bb.z;
                st[j * 4 + 3] += coef * bb.w;
            }
        }
        float* sp = states + (((size_t)(b * NC + c) * HS) + h) * PD * DS + (size_t)p * DS + n0;
        #pragma unroll
        for (int i = 0; i < 32; i++) sp[i] = st[i];
    }
}

// ---------------- cross-chunk prefix: states -> states_prev (in place) ----------------
__global__ void __launch_bounds__(256)
ssd_prefix(float* __restrict__ states, const float* __restrict__ Asum)
{
    int h = blockIdx.x, b = blockIdx.y;
    float dec[NC];
    #pragma unroll
    for (int c = 0; c < NC; c++) dec[c] = expf(Asum[(b * HS + h) * NC + c]);
    for (int idx = threadIdx.x; idx < PD * DS; idx += blockDim.x) {
        float S = 0.f;
        #pragma unroll
        for (int c = 0; c < NC; c++) {
            size_t off = (((size_t)(b * NC + c) * HS) + h) * PD * DS + idx;
            float st = states[off];
            states[off] = S;
            S = dec[c] * S + st;
        }
    }
}

// ---------------- SSD part2: Y += expAcs * (C . S_prev) + D*x ----------------
__global__ void __launch_bounds__(256)
ssd_part2(const float* __restrict__ xBC, const float* __restrict__ statesPrev,
          const float* __restrict__ expAcs, const float* __restrict__ D_param,
          float* __restrict__ y)
{
    int h = blockIdx.x, c = blockIdx.y, b = blockIdx.z;
    int l = threadIdx.x;
    int tok0 = b * TSEQ + c * CH;

    __shared__ float sS[16][64];   // [n'][p]

    float acc[64];
    #pragma unroll
    for (int p = 0; p < 64; p++) acc[p] = 0.f;

    const float* Sp = statesPrev + (((size_t)(b * NC + c) * HS) + h) * PD * DS;
    const float* Crow = xBC + (size_t)(tok0 + l) * CONVD + DINNER + DS;

    for (int nt = 0; nt < 8; nt++) {
        int n0 = nt * 16;
        // this thread's 16 C values
        float cre[16];
        {
            const float4* cp = (const float4*)(Crow + n0);
            #pragma unroll
            for (int q4 = 0; q4 < 4; q4++) {
                float4 vv = cp[q4];
                cre[q4 * 4 + 0] = vv.x; cre[q4 * 4 + 1] = vv.y;
                cre[q4 * 4 + 2] = vv.z; cre[q4 * 4 + 3] = vv.w;
            }
        }
        __syncthreads();
        // stage S_prev slice [16 n'][64 p]
        for (int i = l; i < 16 * 64; i += 256) {
            int nn = i & 15, p = i >> 4;
            sS[nn][p] = Sp[(size_t)p * DS + n0 + nn];
        }
        __syncthreads();
        #pragma unroll
        for (int nn = 0; nn < 16; nn++) {
            float cv = cre[nn];
            const float4* sr = (const float4*)sS[nn];
            #pragma unroll
            for (int p4 = 0; p4 < 16; p4++) {
                float4 sv = sr[p4];
                acc[p4 * 4 + 0] += cv * sv.x;
                acc[p4 * 4 + 1] += cv * sv.y;
                acc[p4 * 4 + 2] += cv * sv.z;
                acc[p4 * 4 + 3] += cv * sv.w;
            }
        }
    }

    float eA = expAcs[(((size_t)(b * NC + c) * HS) + h) * CH + l];
    float Dp = D_param[h];
    size_t ybase = (size_t)(tok0 + l) * DINNER + h * PD;
    size_t xbase = (size_t)(tok0 + l) * CONVD + h * PD;
    #pragma unroll
    for (int p = 0; p < 64; p++) {
        float xv = xBC[xbase + p];
        y[ybase + p] = y[ybase + p] + eA * acc[p] + Dp * xv;
    }
}

// ---------------- gated rmsnorm: yg = rmsnorm(y * silu(z)) * w ----------------
__global__ void __launch_bounds__(256)
gate_norm_kernel(const float* __restrict__ y, const float* __restrict__ zx,
                 const float* __restrict__ w, float* __restrict__ out)
{
    int tok = blockIdx.x, tid = threadIdx.x;
    __shared__ float red[8];
    float g[8];
    float ss = 0.f;
    #pragma unroll
    for (int u = 0; u < 8; u++) {
        int d = tid + u * 256;
        float z  = zx[(size_t)tok * DIP + d];
        float yy = y[(size_t)tok * DINNER + d];
        float gv = yy * (z / (1.f + expf(-z)));
        g[u] = gv;
        ss += gv * gv;
    }
    float total = block_sum256(ss, red);
    float sc = rsqrtf(total * (1.f / DINNER) + 1e-5f);
    #pragma unroll
    for (int u = 0; u < 8; u++) {
        int d = tid + u * 256;
        out[(size_t)tok * DINNER + d] = g[u] * sc * w[d];
    }
}

// ---------------- launch ----------------
extern "C" void kernel_launch(void* const* d_in, const int* in_sizes, int n_in,
                              void* d_out, int out_size)
{
    const float* x         = (const float*)d_in[0];
    const float* W_in      = (const float*)d_in[1];
    const float* W_z       = (const float*)d_in[2];
    const float* conv_w    = (const float*)d_in[3];
    const float* conv_b    = (const float*)d_in[4];
    const float* dt_bias   = (const float*)d_in[5];
    const float* A_log     = (const float*)d_in[6];
    const float* D_param   = (const float*)d_in[7];
    const float* norm_pre  = (const float*)d_in[8];
    const float* norm_gate = (const float*)d_in[9];
    const float* W_out     = (const float*)d_in[10];
    float* out = (float*)d_out;

    float* sc = nullptr;
    cudaGetSymbolAddress((void**)&sc, g_scratch);

    // 1) q = x @ W_in[:1024].T   (k,v never used by the reference)
    gemm_nt<<<dim3(DM / 64, NTOK / 64, 1), 256>>>(
        x, W_in, sc + OFF_Q, nullptr, NTOK, DM, DM, DM, DM, DM, 0, 0, 0);

    // 2) rope (in place -> residual) + rmsnorm -> h
    rope_norm_kernel<<<NTOK, 256>>>(sc + OFF_Q, sc + OFF_H, norm_pre);

    // 3) zxbcdt = h @ W_zxbcdt.T
    gemm_nt<<<dim3((DIP + 63) / 64, NTOK / 64, 1), 256>>>(
        sc + OFF_H, W_z, sc + OFF_ZX, nullptr, NTOK, DIP, DM, DM, DM, DIP, 0, 0, 0);

    // 4) dt
    dt_kernel<<<(NTOK * HS + 255) / 256, 256>>>(sc + OFF_ZX, dt_bias, sc + OFF_DT);

    // 5) conv + silu
    conv_kernel<<<(NTOK * CONVD + 255) / 256, 256>>>(sc + OFF_ZX, conv_w, conv_b, sc + OFF_XBC);

    // 6) G^T[s][l] = B_s . C_l, batched over 16 (b,c) chunks (h-independent!)
    gemm_nt<<<dim3(4, 4, 16), 256>>>(
        sc + OFF_XBC + DINNER, sc + OFF_XBC + DINNER + DS, sc + OFF_G, nullptr,
        CH, CH, DS, CONVD, CONVD, CH,
        (size_t)CH * CONVD, (size_t)CH * CONVD, (size_t)CH * CH);

    // 7) SSD: Y_diag + chunk states
    ssd_part1<<<dim3(HS, NC, 2), 256>>>(
        sc + OFF_XBC, sc + OFF_DT, A_log, sc + OFF_G,
        sc + OFF_Y, sc + OFF_ST, sc + OFF_ASUM, sc + OFF_EACS);

    // 8) cross-chunk prefix (states -> states_prev)
    ssd_prefix<<<dim3(HS, 2), 256>>>(sc + OFF_ST, sc + OFF_ASUM);

    // 9) Y += exp(Acs) * (C . S_prev) + D * x
    ssd_part2<<<dim3(HS, NC, 2), 256>>>(
        sc + OFF_XBC, sc + OFF_ST, sc + OFF_EACS, D_param, sc + OFF_Y);

    // 10) gated rmsnorm
    gate_norm_kernel<<<NTOK, 256>>>(sc + OFF_Y, sc + OFF_ZX, norm_gate, sc + OFF_YG);

    // 11) out = yg @ W_out.T + residual
    gemm_nt<<<dim3(DM / 64, NTOK / 64, 1), 256>>>(
        sc + OFF_YG, W_out, out, sc + OFF_Q, NTOK, DM, DINNER, DINNER, DINNER, DM, 0, 0, 0);
}

// round 4
// speedup vs baseline: 1.6088x; 1.6088x over previous
#include <cuda_runtime.h>
#include <cuda_bf16.h>
#include <math.h>
#include <stdint.h>

// ---------------- problem constants ----------------
#define NTOK   4096          // N*T = 2*2048
#define TSEQ   2048
#define DM     1024          // d_model
#define DIP    4384          // d_in_proj
#define DINNER 2048
#define CONVD  2304          // d_inner + 2*d_state
#define HS     32            // ssm heads
#define PD     64            // headdim
#define DS     128           // d_state
#define CH     256           // chunk
#define NC     8             // chunks per sequence

// ---------------- scratch layout (floats) ----------------
#define OFF_Q    0ull                 // 4096*1024   roped q (residual)
#define OFF_H    4194304ull           // 4096*1024   rmsnormed h
#define OFF_ZX   8388608ull           // 4096*4384   zxbcdt
#define OFF_XBC  26345472ull          // 4096*2304   conv+silu output
#define OFF_DT   35782656ull          // 4096*32     softplus dt
#define OFF_G    35913728ull          // 16*256*256  G^T per (b,c): [s][l]
#define OFF_ST   36962304ull          // 16*32*64*128 chunk states -> states_prev
#define OFF_ASUM 41156608ull          // 2*32*8      chunk A sums
#define OFF_EACS 41157120ull          // 16*32*256   exp(Acs)
#define OFF_Y    41288192ull          // 4096*2048   y
#define OFF_YG   49676800ull          // 4096*2048   gated normed y
#define SCRATCH_FLOATS 58065408ull

__device__ float g_scratch[SCRATCH_FLOATS];

// =====================================================================
//  mma.sync helpers (base-target PTX, compiles to HMMA on sm_100)
// =====================================================================
__device__ __forceinline__ uint32_t sm32(const void* p) {
    return (uint32_t)__cvta_generic_to_shared(p);
}
__device__ __forceinline__ void ldsm_x4(uint32_t& r0, uint32_t& r1, uint32_t& r2, uint32_t& r3,
                                        uint32_t a) {
    asm volatile("ldmatrix.sync.aligned.m8n8.x4.shared.b16 {%0,%1,%2,%3}, [%4];"
                 : "=r"(r0), "=r"(r1), "=r"(r2), "=r"(r3) : "r"(a));
}
__device__ __forceinline__ void ldsm_x2(uint32_t& r0, uint32_t& r1, uint32_t a) {
    asm volatile("ldmatrix.sync.aligned.m8n8.x2.shared.b16 {%0,%1}, [%2];"
                 : "=r"(r0), "=r"(r1) : "r"(a));
}
__device__ __forceinline__ void mma16816(float* c, const uint32_t* a, uint32_t b0, uint32_t b1) {
    asm volatile(
        "mma.sync.aligned.m16n8k16.row.col.f32.bf16.bf16.f32 "
        "{%0,%1,%2,%3}, {%4,%5,%6,%7}, {%8,%9}, {%0,%1,%2,%3};"
        : "+f"(c[0]), "+f"(c[1]), "+f"(c[2]), "+f"(c[3])
        : "r"(a[0]), "r"(a[1]), "r"(a[2]), "r"(a[3]), "r"(b0), "r"(b1));
}
__device__ __forceinline__ uint32_t pack2(float x0, float x1) {
    __nv_bfloat16 h0 = __float2bfloat16_rn(x0);
    __nv_bfloat16 h1 = __float2bfloat16_rn(x1);
    return (uint32_t)__bfloat16_as_ushort(h0) | ((uint32_t)__bfloat16_as_ushort(h1) << 16);
}
// split float pair -> (hi pair, lo pair)
__device__ __forceinline__ void split2(float x0, float x1, uint32_t& hi, uint32_t& lo) {
    __nv_bfloat16 h0 = __float2bfloat16_rn(x0);
    __nv_bfloat16 h1 = __float2bfloat16_rn(x1);
    float r0 = x0 - __bfloat162float(h0);
    float r1 = x1 - __bfloat162float(h1);
    hi = (uint32_t)__bfloat16_as_ushort(h0) | ((uint32_t)__bfloat16_as_ushort(h1) << 16);
    lo = pack2(r0, r1);
}

// =====================================================================
//  tensor-core GEMM via 3-product bf16 split:  C = A(MxK)*B(NxK)^T (+addC)
//  128x128 tile/CTA, BK=32, 256 threads = 8 warps (4 x 2), warp = 32x64
//  M must be a multiple of 128; N arbitrary; K multiple of 32.
// =====================================================================
#define BM 128
#define BN 128
#define BK 32
#define LDK 40   // bf16 elements per smem row (32 + 8 pad)

__global__ void __launch_bounds__(256)
gemm_mma(const float* __restrict__ A, const float* __restrict__ B,
         float* __restrict__ C, const float* __restrict__ addC,
         int M, int N, int K, int lda, int ldb, int ldc,
         size_t bsA, size_t bsB, size_t bsC)
{
    __shared__ __nv_bfloat16 sAh[BM * LDK];
    __shared__ __nv_bfloat16 sAl[BM * LDK];
    __shared__ __nv_bfloat16 sBh[BM * LDK];
    __shared__ __nv_bfloat16 sBl[BM * LDK];

    A += bsA * blockIdx.z;
    B += bsB * blockIdx.z;
    C += bsC * blockIdx.z;

    int tid = threadIdx.x, lane = tid & 31, wid = tid >> 5;
    int warp_m = wid & 3, warp_n = wid >> 2;       // 4 x 2 warp grid
    int m0 = blockIdx.y * BM, n0 = blockIdx.x * BN;

    float acc[2][8][4];
    #pragma unroll
    for (int mt = 0; mt < 2; mt++)
        #pragma unroll
        for (int nt = 0; nt < 8; nt++)
            #pragma unroll
            for (int e = 0; e < 4; e++) acc[mt][nt][e] = 0.f;

    // load assignment: thread -> (row = tid/2, 16-float half = (tid&1)*16)
    int lrow = tid >> 1;
    int lf   = (tid & 1) * 16;
    const float* arow = A + (size_t)(m0 + lrow) * lda + lf;
    const float* brow = B + (size_t)(n0 + lrow) * ldb + lf;
    const bool bval = (n0 + lrow) < N;

    // ldmatrix source addresses (fixed per thread)
    int a_r = (lane & 15), a_k = ((lane >> 4) << 3);
    int b_r = (lane & 7),  b_k = (((lane >> 3) & 1) << 3);

    for (int kc = 0; kc < K; kc += BK) {
        __syncthreads();
        #pragma unroll
        for (int j = 0; j < 4; j++) {
            float4 va = *(const float4*)(arow + kc + j * 4);
            uint32_t h, l;
            int so = lrow * LDK + lf + j * 4;
            split2(va.x, va.y, h, l);
            *(uint32_t*)&sAh[so] = h; *(uint32_t*)&sAl[so] = l;
            split2(va.z, va.w, h, l);
            *(uint32_t*)&sAh[so + 2] = h; *(uint32_t*)&sAl[so + 2] = l;

            float4 vb = bval ? *(const float4*)(brow + kc + j * 4)
                             : make_float4(0.f, 0.f, 0.f, 0.f);
            split2(vb.x, vb.y, h, l);
            *(uint32_t*)&sBh[so] = h; *(uint32_t*)&sBl[so] = l;
            split2(vb.z, vb.w, h, l);
            *(uint32_t*)&sBh[so + 2] = h; *(uint32_t*)&sBl[so + 2] = l;
        }
        __syncthreads();

        #pragma unroll
        for (int ks = 0; ks < 2; ks++) {
            int k0 = ks * 16;
            uint32_t ah[2][4], al[2][4];
            #pragma unroll
            for (int mt = 0; mt < 2; mt++) {
                int ar = (warp_m * 32 + mt * 16 + a_r) * LDK + k0 + a_k;
                ldsm_x4(ah[mt][0], ah[mt][1], ah[mt][2], ah[mt][3], sm32(&sAh[ar]));
                ldsm_x4(al[mt][0], al[mt][1], al[mt][2], al[mt][3], sm32(&sAl[ar]));
            }
            #pragma unroll
            for (int nt = 0; nt < 8; nt++) {
                int br = (warp_n * 64 + nt * 8 + b_r) * LDK + k0 + b_k;
                uint32_t bh0, bh1, bl0, bl1;
                ldsm_x2(bh0, bh1, sm32(&sBh[br]));
                ldsm_x2(bl0, bl1, sm32(&sBl[br]));
                #pragma unroll
                for (int mt = 0; mt < 2; mt++) {
                    mma16816(acc[mt][nt], ah[mt], bh0, bh1);   // hi*hi
                    mma16816(acc[mt][nt], ah[mt], bl0, bl1);   // hi*lo
                    mma16816(acc[mt][nt], al[mt], bh0, bh1);   // lo*hi
                }
            }
        }
    }

    // epilogue (M always multiple of 128 here; guard N only)
    int tg = lane >> 2, tq = lane & 3;
    #pragma unroll
    for (int mt = 0; mt < 2; mt++) {
        int m = m0 + warp_m * 32 + mt * 16 + tg;
        #pragma unroll
        for (int nt = 0; nt < 8; nt++) {
            int n = n0 + warp_n * 64 + nt * 8 + tq * 2;
            if (n < N) {
                size_t o0 = (size_t)m * ldc + n;
                size_t o1 = (size_t)(m + 8) * ldc + n;
                float v0 = acc[mt][nt][0], v1 = acc[mt][nt][1];
                float v2 = acc[mt][nt][2], v3 = acc[mt][nt][3];
                if (addC) {
                    v0 += addC[o0]; v1 += addC[o0 + 1];
                    v2 += addC[o1]; v3 += addC[o1 + 1];
                }
                C[o0] = v0; C[o0 + 1] = v1;
                C[o1] = v2; C[o1 + 1] = v3;
            }
        }
    }
}

// =====================================================================
//  remaining (SIMT) kernels — unchanged from the passing R2 build
// =====================================================================
__device__ __forceinline__ float block_sum256(float v, float* red) {
    #pragma unroll
    for (int o = 16; o; o >>= 1) v += __shfl_down_sync(0xffffffffu, v, o);
    int lane = threadIdx.x & 31, wid = threadIdx.x >> 5;
    if (lane == 0) red[wid] = v;
    __syncthreads();
    if (wid == 0) {
        float w = (lane < 8) ? red[lane] : 0.f;
        #pragma unroll
        for (int o = 16; o; o >>= 1) w += __shfl_down_sync(0xffffffffu, w, o);
        if (lane == 0) red[0] = w;
    }
    __syncthreads();
    return red[0];
}

__global__ void __launch_bounds__(256)
rope_norm_kernel(float* __restrict__ q, float* __restrict__ h,
                 const float* __restrict__ w)
{
    int tok = blockIdx.x;
    int t = tok & (TSEQ - 1);
    __shared__ float row[DM];
    __shared__ float red[8];
    int tid = threadIdx.x;
    for (int i = tid; i < DM; i += 256) row[i] = q[(size_t)tok * DM + i];
    __syncthreads();

    float vals[4];
    float ss = 0.f;
    #pragma unroll
    for (int u = 0; u < 4; u++) {
        int d  = tid + u * 256;
        int hd = d & 63;
        int i  = hd & 31;
        float inv = exp2f(-(float)(2 * i) * (1.f / 64.f) * 13.287712379549449f);
        float ang = (float)t * inv;
        float c, s;
        sincosf(ang, &s, &c);
        float v;
        if (hd < 32) { float q1 = row[d], q2 = row[d + 32]; v = q1 * c - q2 * s; }
        else         { float q2 = row[d], q1 = row[d - 32]; v = q2 * c + q1 * s; }
        vals[u] = v;
        ss += v * v;
    }
    float total = block_sum256(ss, red);
    float scale = rsqrtf(total * (1.f / DM) + 1e-5f);
    #pragma unroll
    for (int u = 0; u < 4; u++) {
        int d = tid + u * 256;
        q[(size_t)tok * DM + d] = vals[u];
        h[(size_t)tok * DM + d] = vals[u] * scale * w[d];
    }
}

__global__ void __launch_bounds__(256)
dt_kernel(const float* __restrict__ zx, const float* __restrict__ dtb,
          float* __restrict__ dt)
{
    int idx = blockIdx.x * blockDim.x + threadIdx.x;
    if (idx >= NTOK * HS) return;
    int tok = idx >> 5, hh = idx & 31;
    float x = zx[(size_t)tok * DIP + (DIP - HS) + hh] + dtb[hh];
    float sp = (x > 20.f) ? x : log1pf(expf(x));
    dt[idx] = sp;
}

__global__ void __launch_bounds__(256)
conv_kernel(const float* __restrict__ zx, const float* __restrict__ cw,
            const float* __restrict__ cb, float* __restrict__ out)
{
    int idx = blockIdx.x * blockDim.x + threadIdx.x;
    if (idx >= NTOK * CONVD) return;
    int tok = idx / CONVD, ch = idx % CONVD;
    int t = tok & (TSEQ - 1);
    float acc = cb[ch];
    #pragma unroll
    for (int k = 0; k < 4; k++) {
        int tt = t + k - 3;
        if (tt >= 0) acc += zx[(size_t)(tok + k - 3) * DIP + DINNER + ch] * cw[ch * 4 + k];
    }
    float sg = 1.f / (1.f + expf(-acc));
    out[(size_t)tok * CONVD + ch] = acc * sg;
}

__global__ void __launch_bounds__(256)
ssd_part1(const float* __restrict__ xBC, const float* __restrict__ dt,
          const float* __restrict__ A_log, const float* __restrict__ G,
          float* __restrict__ y, float* __restrict__ states,
          float* __restrict__ Asum, float* __restrict__ expAcs)
{
    int h = blockIdx.x, c = blockIdx.y, b = blockIdx.z;
    int l = threadIdx.x;
    int tok0 = b * TSEQ + c * CH;

    __shared__ float sAcs[CH];
    __shared__ float sDt[CH];
    __shared__ float sDec[CH];
    __shared__ float sES[64];
    __shared__ float sX[64][64];
    __shared__ float warpsum[8];

    float dtl = dt[(size_t)(tok0 + l) * HS + h];
    float A   = -expf(A_log[h]);
    float adt = dtl * A;

    int lane = l & 31, wid = l >> 5;
    float v = adt;
    #pragma unroll
    for (int o = 1; o < 32; o <<= 1) {
        float u = __shfl_up_sync(0xffffffffu, v, o);
        if (lane >= o) v += u;
    }
    if (lane == 31) warpsum[wid] = v;
    __syncthreads();
    if (wid == 0) {
        float w = (lane < 8) ? warpsum[lane] : 0.f;
        #pragma unroll
        for (int o = 1; o < 8; o <<= 1) {
            float u = __shfl_up_sync(0xffffffffu, w, o);
            if (lane >= o) w += u;
        }
        if (lane < 8) warpsum[lane] = w;
    }
    __syncthreads();
    float acs   = v + ((wid > 0) ? warpsum[wid - 1] : 0.f);
    float total = warpsum[7];

    sAcs[l] = acs;
    sDt[l]  = dtl;
    sDec[l] = expf(total - acs);
    expAcs[(((size_t)(b * NC + c) * HS) + h) * CH + l] = expf(acs);
    if (l == 0) Asum[(b * HS + h) * NC + c] = total;
    __syncthreads();

    const float* Gp = G + ((size_t)(b * NC + c)) * CH * CH;

    float acc[64];
    #pragma unroll
    for (int p = 0; p < 64; p++) acc[p] = 0.f;

    for (int t4 = 0; t4 < 4; t4++) {
        int sbase = t4 * 64;
        __syncthreads();
        for (int i = l; i < 64 * 64; i += 256) {
            int r = i >> 6, cc2 = i & 63;
            sX[r][cc2] = xBC[(size_t)(tok0 + sbase + r) * CONVD + h * PD + cc2] * sDt[sbase + r];
        }
        if (l < 64) sES[l] = expf(sAcs[sbase + 63] - sAcs[sbase + l]);
        __syncthreads();

        if (sbase + 63 < l) {
            float f = expf(sAcs[l] - sAcs[sbase + 63]);
            for (int s = 0; s < 64; s++) {
                float w = Gp[(size_t)(sbase + s) * CH + l] * (f * sES[s]);
                const float4* xr = (const float4*)sX[s];
                #pragma unroll
                for (int p4 = 0; p4 < 16; p4++) {
                    float4 xx = xr[p4];
                    acc[p4 * 4 + 0] += w * xx.x;
                    acc[p4 * 4 + 1] += w * xx.y;
                    acc[p4 * 4 + 2] += w * xx.z;
                    acc[p4 * 4 + 3] += w * xx.w;
                }
            }
        } else if (sbase <= l) {
            for (int s = sbase; s <= l; s++) {
                float w = Gp[(size_t)s * CH + l] * expf(sAcs[l] - sAcs[s]);
                const float4* xr = (const float4*)sX[s - sbase];
                #pragma unroll
                for (int p4 = 0; p4 < 16; p4++) {
                    float4 xx = xr[p4];
                    acc[p4 * 4 + 0] += w * xx.x;
                    acc[p4 * 4 + 1] += w * xx.y;
                    acc[p4 * 4 + 2] += w * xx.z;
                    acc[p4 * 4 + 3] += w * xx.w;
                }
            }
        }
    }

    #pragma unroll
    for (int p = 0; p < 64; p++)
        y[(size_t)(tok0 + l) * DINNER + h * PD + p] = acc[p];
    __syncthreads();

    {
        int p  = l >> 2;
        int n0 = (l & 3) * 32;
        float st[32];
        #pragma unroll
        for (int i = 0; i < 32; i++) st[i] = 0.f;
        for (int ll = 0; ll < CH; ll++) {
            float coef = sDec[ll] * sDt[ll] * xBC[(size_t)(tok0 + ll) * CONVD + h * PD + p];
            const float4* bp = (const float4*)(xBC + (size_t)(tok0 + ll) * CONVD + DINNER + n0);
            #pragma unroll
            for (int j = 0; j < 8; j++) {
                float4 bb = bp[j];
                st[j * 4 + 0] += coef * bb.x;
                st[j * 4 + 1] += coef * bb.y;
                st[j * 4 + 2] += coef * bb.z;
                st[j * 4 + 3] += coef * bb.w;
            }
        }
        float* sp = states + (((size_t)(b * NC + c) * HS) + h) * PD * DS + (size_t)p * DS + n0;
        #pragma unroll
        for (int i = 0; i < 32; i++) sp[i] = st[i];
    }
}

__global__ void __launch_bounds__(256)
ssd_prefix(float* __restrict__ states, const float* __restrict__ Asum)
{
    int h = blockIdx.x, b = blockIdx.y;
    float dec[NC];
    #pragma unroll
    for (int c = 0; c < NC; c++) dec[c] = expf(Asum[(b * HS + h) * NC + c]);
    for (int idx = threadIdx.x; idx < PD * DS; idx += blockDim.x) {
        float S = 0.f;
        #pragma unroll
        for (int c = 0; c < NC; c++) {
            size_t off = (((size_t)(b * NC + c) * HS) + h) * PD * DS + idx;
            float st = states[off];
            states[off] = S;
            S = dec[c] * S + st;
        }
    }
}

__global__ void __launch_bounds__(256)
ssd_part2(const float* __restrict__ xBC, const float* __restrict__ statesPrev,
          const float* __restrict__ expAcs, const float* __restrict__ D_param,
          float* __restrict__ y)
{
    int h = blockIdx.x, c = blockIdx.y, b = blockIdx.z;
    int l = threadIdx.x;
    int tok0 = b * TSEQ + c * CH;

    __shared__ float sS[16][64];

    float acc[64];
    #pragma unroll
    for (int p = 0; p < 64; p++) acc[p] = 0.f;

    const float* Sp = statesPrev + (((size_t)(b * NC + c) * HS) + h) * PD * DS;
    const float* Crow = xBC + (size_t)(tok0 + l) * CONVD + DINNER + DS;

    for (int nt = 0; nt < 8; nt++) {
        int n0 = nt * 16;
        float cre[16];
        {
            const float4* cp = (const float4*)(Crow + n0);
            #pragma unroll
            for (int q4 = 0; q4 < 4; q4++) {
                float4 vv = cp[q4];
                cre[q4 * 4 + 0] = vv.x; cre[q4 * 4 + 1] = vv.y;
                cre[q4 * 4 + 2] = vv.z; cre[q4 * 4 + 3] = vv.w;
            }
        }
        __syncthreads();
        for (int i = l; i < 16 * 64; i += 256) {
            int nn = i & 15, p = i >> 4;
            sS[nn][p] = Sp[(size_t)p * DS + n0 + nn];
        }
        __syncthreads();
        #pragma unroll
        for (int nn = 0; nn < 16; nn++) {
            float cv = cre[nn];
            const float4* sr = (const float4*)sS[nn];
            #pragma unroll
            for (int p4 = 0; p4 < 16; p4++) {
                float4 sv = sr[p4];
                acc[p4 * 4 + 0] += cv * sv.x;
                acc[p4 * 4 + 1] += cv * sv.y;
                acc[p4 * 4 + 2] += cv * sv.z;
                acc[p4 * 4 + 3] += cv * sv.w;
            }
        }
    }

    float eA = expAcs[(((size_t)(b * NC + c) * HS) + h) * CH + l];
    float Dp = D_param[h];
    size_t ybase = (size_t)(tok0 + l) * DINNER + h * PD;
    size_t xbase = (size_t)(tok0 + l) * CONVD + h * PD;
    #pragma unroll
    for (int p = 0; p < 64; p++) {
        float xv = xBC[xbase + p];
        y[ybase + p] = y[ybase + p] + eA * acc[p] + Dp * xv;
    }
}

__global__ void __launch_bounds__(256)
gate_norm_kernel(const float* __restrict__ y, const float* __restrict__ zx,
                 const float* __restrict__ w, float* __restrict__ out)
{
    int tok = blockIdx.x, tid = threadIdx.x;
    __shared__ float red[8];
    float g[8];
    float ss = 0.f;
    #pragma unroll
    for (int u = 0; u < 8; u++) {
        int d = tid + u * 256;
        float z  = zx[(size_t)tok * DIP + d];
        float yy = y[(size_t)tok * DINNER + d];
        float gv = yy * (z / (1.f + expf(-z)));
        g[u] = gv;
        ss += gv * gv;
    }
    float total = block_sum256(ss, red);
    float sc = rsqrtf(total * (1.f / DINNER) + 1e-5f);
    #pragma unroll
    for (int u = 0; u < 8; u++) {
        int d = tid + u * 256;
        out[(size_t)tok * DINNER + d] = g[u] * sc * w[d];
    }
}

// ---------------- launch ----------------
extern "C" void kernel_launch(void* const* d_in, const int* in_sizes, int n_in,
                              void* d_out, int out_size)
{
    const float* x         = (const float*)d_in[0];
    const float* W_in      = (const float*)d_in[1];
    const float* W_z       = (const float*)d_in[2];
    const float* conv_w    = (const float*)d_in[3];
    const float* conv_b    = (const float*)d_in[4];
    const float* dt_bias   = (const float*)d_in[5];
    const float* A_log     = (const float*)d_in[6];
    const float* D_param   = (const float*)d_in[7];
    const float* norm_pre  = (const float*)d_in[8];
    const float* norm_gate = (const float*)d_in[9];
    const float* W_out     = (const float*)d_in[10];
    float* out = (float*)d_out;

    float* sc = nullptr;
    cudaGetSymbolAddress((void**)&sc, g_scratch);

    // 1) q = x @ W_in[:1024].T   (k,v never used by the reference)
    gemm_mma<<<dim3(DM / BN, NTOK / BM, 1), 256>>>(
        x, W_in, sc + OFF_Q, nullptr, NTOK, DM, DM, DM, DM, DM, 0, 0, 0);

    // 2) rope (in place -> residual) + rmsnorm -> h
    rope_norm_kernel<<<NTOK, 256>>>(sc + OFF_Q, sc + OFF_H, norm_pre);

    // 3) zxbcdt = h @ W_zxbcdt.T
    gemm_mma<<<dim3((DIP + BN - 1) / BN, NTOK / BM, 1), 256>>>(
        sc + OFF_H, W_z, sc + OFF_ZX, nullptr, NTOK, DIP, DM, DM, DM, DIP, 0, 0, 0);

    // 4) dt
    dt_kernel<<<(NTOK * HS + 255) / 256, 256>>>(sc + OFF_ZX, dt_bias, sc + OFF_DT);

    // 5) conv + silu
    conv_kernel<<<(NTOK * CONVD + 255) / 256, 256>>>(sc + OFF_ZX, conv_w, conv_b, sc + OFF_XBC);

    // 6) G^T[s][l] = B_s . C_l, batched over 16 (b,c) chunks (h-independent!)
    gemm_mma<<<dim3(CH / BN, CH / BM, 16), 256>>>(
        sc + OFF_XBC + DINNER, sc + OFF_XBC + DINNER + DS, sc + OFF_G, nullptr,
        CH, CH, DS, CONVD, CONVD, CH,
        (size_t)CH * CONVD, (size_t)CH * CONVD, (size_t)CH * CH);

    // 7) SSD: Y_diag + chunk states
    ssd_part1<<<dim3(HS, NC, 2), 256>>>(
        sc + OFF_XBC, sc + OFF_DT, A_log, sc + OFF_G,
        sc + OFF_Y, sc + OFF_ST, sc + OFF_ASUM, sc + OFF_EACS);

    // 8) cross-chunk prefix (states -> states_prev)
    ssd_prefix<<<dim3(HS, 2), 256>>>(sc + OFF_ST, sc + OFF_ASUM);

    // 9) Y += exp(Acs) * (C . S_prev) + D * x
    ssd_part2<<<dim3(HS, NC, 2), 256>>>(
        sc + OFF_XBC, sc + OFF_ST, sc + OFF_EACS, D_param, sc + OFF_Y);

    // 10) gated rmsnorm
    gate_norm_kernel<<<NTOK, 256>>>(sc + OFF_Y, sc + OFF_ZX, norm_gate, sc + OFF_YG);

    // 11) out = yg @ W_out.T + residual
    gemm_mma<<<dim3(DM / BN, NTOK / BM, 1), 256>>>(
        sc + OFF_YG, W_out, out, sc + OFF_Q, NTOK, DM, DINNER, DINNER, DINNER, DM, 0, 0, 0);
}

// round 5
// speedup vs baseline: 1.7529x; 1.0896x over previous
#include <cuda_runtime.h>
#include <cuda_bf16.h>
#include <math.h>
#include <stdint.h>

// ---------------- problem constants ----------------
#define NTOK   4096          // N*T = 2*2048
#define TSEQ   2048
#define DM     1024          // d_model
#define DIP    4384          // d_in_proj
#define DINNER 2048
#define CONVD  2304          // d_inner + 2*d_state
#define HS     32            // ssm heads
#define PD     64            // headdim
#define DS     128           // d_state
#define CH     256           // chunk
#define NC     8             // chunks per sequence

// ---------------- scratch layout (floats) ----------------
#define OFF_Q    0ull                 // 4096*1024   roped q (residual)
#define OFF_ZX   8388608ull           // 4096*4384   zxbcdt
#define OFF_XBC  26345472ull          // 4096*2304   conv+silu output
#define OFF_DT   35782656ull          // 4096*32     softplus dt
#define OFF_G    35913728ull          // 16*256*256  G^T per (b,c): [s][l]
#define OFF_ST   36962304ull          // 16*32*64*128 chunk states -> states_prev
#define OFF_ASUM 41156608ull          // 2*32*8      chunk A sums
#define OFF_EACS 41157120ull          // 16*32*256   exp(Acs)
#define OFF_Y    41288192ull          // 4096*2048   y
// bf16 hi/lo arrays (offsets in floats; 1 float = 2 bf16)
#define OFF_XHI  58065408ull
#define OFF_XLO  60162560ull
#define OFF_WIH  62259712ull
#define OFF_WIL  62784000ull
#define OFF_WZH  63308288ull
#define OFF_WZL  65552896ull
#define OFF_WOH  67797504ull
#define OFF_WOL  68846080ull
#define OFF_HH   69894656ull
#define OFF_HL   71991808ull
#define OFF_YGH  74088960ull
#define OFF_YGL  78283264ull
#define OFF_BCH  82477568ull
#define OFF_BCL  83001856ull
#define SCRATCH_FLOATS 83526144ull

__device__ float g_scratch[SCRATCH_FLOATS];

typedef __nv_bfloat16 bf16;

// =====================================================================
//  helpers
// =====================================================================
__device__ __forceinline__ uint32_t sm32(const void* p) {
    return (uint32_t)__cvta_generic_to_shared(p);
}
__device__ __forceinline__ void ldsm_x4(uint32_t& r0, uint32_t& r1, uint32_t& r2, uint32_t& r3,
                                        uint32_t a) {
    asm volatile("ldmatrix.sync.aligned.m8n8.x4.shared.b16 {%0,%1,%2,%3}, [%4];"
                 : "=r"(r0), "=r"(r1), "=r"(r2), "=r"(r3) : "r"(a));
}
__device__ __forceinline__ void ldsm_x2(uint32_t& r0, uint32_t& r1, uint32_t a) {
    asm volatile("ldmatrix.sync.aligned.m8n8.x2.shared.b16 {%0,%1}, [%2];"
                 : "=r"(r0), "=r"(r1) : "r"(a));
}
__device__ __forceinline__ void mma16816(float* c, const uint32_t* a, uint32_t b0, uint32_t b1) {
    asm volatile(
        "mma.sync.aligned.m16n8k16.row.col.f32.bf16.bf16.f32 "
        "{%0,%1,%2,%3}, {%4,%5,%6,%7}, {%8,%9}, {%0,%1,%2,%3};"
        : "+f"(c[0]), "+f"(c[1]), "+f"(c[2]), "+f"(c[3])
        : "r"(a[0]), "r"(a[1]), "r"(a[2]), "r"(a[3]), "r"(b0), "r"(b1));
}
__device__ __forceinline__ uint32_t pack2(float x0, float x1) {
    bf16 h0 = __float2bfloat16_rn(x0);
    bf16 h1 = __float2bfloat16_rn(x1);
    return (uint32_t)__bfloat16_as_ushort(h0) | ((uint32_t)__bfloat16_as_ushort(h1) << 16);
}
__device__ __forceinline__ void split2(float x0, float x1, uint32_t& hi, uint32_t& lo) {
    bf16 h0 = __float2bfloat16_rn(x0);
    bf16 h1 = __float2bfloat16_rn(x1);
    hi = (uint32_t)__bfloat16_as_ushort(h0) | ((uint32_t)__bfloat16_as_ushort(h1) << 16);
    lo = pack2(x0 - __bfloat162float(h0), x1 - __bfloat162float(h1));
}
__device__ __forceinline__ void split1(float x, bf16* hi, bf16* lo) {
    bf16 h = __float2bfloat16_rn(x);
    *hi = h;
    *lo = __float2bfloat16_rn(x - __bfloat162float(h));
}
__device__ __forceinline__ void cp16(uint32_t s, const void* g, int bytes) {
    asm volatile("cp.async.cg.shared.global [%0], [%1], 16, %2;"
                 :: "r"(s), "l"(g), "r"(bytes));
}

// ---------------- fp32 -> bf16 hi/lo conversion (elementwise) ----------------
__global__ void __launch_bounds__(256)
cvt_split(const float* __restrict__ in, bf16* __restrict__ hi, bf16* __restrict__ lo, int n4)
{
    int i = blockIdx.x * blockDim.x + threadIdx.x;
    if (i >= n4) return;
    float4 v = ((const float4*)in)[i];
    uint32_t h0, l0, h1, l1;
    split2(v.x, v.y, h0, l0);
    split2(v.z, v.w, h1, l1);
    ((uint2*)hi)[i] = make_uint2(h0, h1);
    ((uint2*)lo)[i] = make_uint2(l0, l1);
}

// =====================================================================
//  pipelined bf16 3-product GEMM:  C = A(MxK)*B(NxK)^T (+addC)
//  operands pre-split into hi/lo bf16.  128x128 tile, BK=32, 256 thr.
// =====================================================================
#define BM 128
#define BN 128
#define BK 32
#define LDK 40                // bf16 per smem row (80 B = 5 x 16 B)
#define MAT  (BM * LDK)       // 5120 bf16 per matrix
#define STG  (4 * MAT)        // Ah, Al, Bh, Bl
#define GEMM_SMEM (2 * STG * 2)   // bytes (2 stages)

__global__ void __launch_bounds__(256)
gemm_bf3(const bf16* __restrict__ Ahi, const bf16* __restrict__ Alo,
         const bf16* __restrict__ Bhi, const bf16* __restrict__ Blo,
         float* __restrict__ C, const float* __restrict__ addC,
         int M, int N, int K, int lda, int ldb, int ldc,
         size_t bsA, size_t bsB, size_t bsC)
{
    extern __shared__ bf16 sm[];

    Ahi += bsA * blockIdx.z; Alo += bsA * blockIdx.z;
    Bhi += bsB * blockIdx.z; Blo += bsB * blockIdx.z;
    C   += bsC * blockIdx.z;

    int tid = threadIdx.x, lane = tid & 31, wid = tid >> 5;
    int warp_m = wid & 3, warp_n = wid >> 2;
    int m0 = blockIdx.y * BM, n0 = blockIdx.x * BN;

    float acc[2][8][4];
    #pragma unroll
    for (int mt = 0; mt < 2; mt++)
        #pragma unroll
        for (int nt = 0; nt < 8; nt++)
            #pragma unroll
            for (int e = 0; e < 4; e++) acc[mt][nt][e] = 0.f;

    const int KC = K >> 5;

    // per-thread load slots: 2 chunks of 16B per matrix
    int r0 = tid >> 2,           k80 = (tid & 3) << 3;
    int r1 = (tid + 256) >> 2,   k81 = k80;           // rows 64..127
    bool bv0 = (n0 + r0) < N, bv1 = (n0 + r1) < N;
    int br0 = bv0 ? r0 : 0, br1 = bv1 ? r1 : 0;

    auto load_stage = [&](int kc, int st) {
        bf16* base = sm + st * STG;
        uint32_t s0 = sm32(base + r0 * LDK + k80);
        uint32_t s1 = sm32(base + r1 * LDK + k81);
        size_t a0 = (size_t)(m0 + r0) * lda + kc + k80;
        size_t a1 = (size_t)(m0 + r1) * lda + kc + k81;
        size_t b0 = (size_t)(n0 + br0) * ldb + kc + k80;
        size_t b1 = (size_t)(n0 + br1) * ldb + kc + k81;
        cp16(s0,                 Ahi + a0, 16);
        cp16(s1,                 Ahi + a1, 16);
        cp16(s0 + 2 * MAT,       Alo + a0, 16);
        cp16(s1 + 2 * MAT,       Alo + a1, 16);
        cp16(s0 + 4 * MAT,       Bhi + b0, bv0 ? 16 : 0);
        cp16(s1 + 4 * MAT,       Bhi + b1, bv1 ? 16 : 0);
        cp16(s0 + 6 * MAT,       Blo + b0, bv0 ? 16 : 0);
        cp16(s1 + 6 * MAT,       Blo + b1, bv1 ? 16 : 0);
    };

    int a_r = (lane & 15), a_k = ((lane >> 4) << 3);
    int b_r = (lane & 7),  b_k = (((lane >> 3) & 1) << 3);

    load_stage(0, 0);
    asm volatile("cp.async.commit_group;");

    for (int c = 0; c < KC; c++) {
        if (c + 1 < KC) {
            load_stage((c + 1) << 5, (c + 1) & 1);
            asm volatile("cp.async.commit_group;");
            asm volatile("cp.async.wait_group 1;");
        } else {
            asm volatile("cp.async.wait_group 0;");
        }
        __syncthreads();

        bf16* base = sm + (c & 1) * STG;
        bf16* sAh = base;
        bf16* sAl = base + MAT;
        bf16* sBh = base + 2 * MAT;
        bf16* sBl = base + 3 * MAT;

        #pragma unroll
        for (int ks = 0; ks < 2; ks++) {
            int k0 = ks * 16;
            uint32_t ah[2][4], al[2][4];
            #pragma unroll
            for (int mt = 0; mt < 2; mt++) {
                int ar = (warp_m * 32 + mt * 16 + a_r) * LDK + k0 + a_k;
                ldsm_x4(ah[mt][0], ah[mt][1], ah[mt][2], ah[mt][3], sm32(&sAh[ar]));
                ldsm_x4(al[mt][0], al[mt][1], al[mt][2], al[mt][3], sm32(&sAl[ar]));
            }
            #pragma unroll
            for (int nt = 0; nt < 8; nt++) {
                int br = (warp_n * 64 + nt * 8 + b_r) * LDK + k0 + b_k;
                uint32_t bh0, bh1, bl0, bl1;
                ldsm_x2(bh0, bh1, sm32(&sBh[br]));
                ldsm_x2(bl0, bl1, sm32(&sBl[br]));
                #pragma unroll
                for (int mt = 0; mt < 2; mt++) {
                    mma16816(acc[mt][nt], ah[mt], bh0, bh1);   // hi*hi
                    mma16816(acc[mt][nt], ah[mt], bl0, bl1);   // hi*lo
                    mma16816(acc[mt][nt], al[mt], bh0, bh1);   // lo*hi
                }
            }
        }
        __syncthreads();
    }

    int tg = lane >> 2, tq = lane & 3;
    #pragma unroll
    for (int mt = 0; mt < 2; mt++) {
        int m = m0 + warp_m * 32 + mt * 16 + tg;
        #pragma unroll
        for (int nt = 0; nt < 8; nt++) {
            int n = n0 + warp_n * 64 + nt * 8 + tq * 2;
            if (n < N) {
                size_t o0 = (size_t)m * ldc + n;
                size_t o1 = (size_t)(m + 8) * ldc + n;
                float v0 = acc[mt][nt][0], v1 = acc[mt][nt][1];
                float v2 = acc[mt][nt][2], v3 = acc[mt][nt][3];
                if (addC) {
                    v0 += addC[o0]; v1 += addC[o0 + 1];
                    v2 += addC[o1]; v3 += addC[o1 + 1];
                }
                C[o0] = v0; C[o0 + 1] = v1;
                C[o1] = v2; C[o1 + 1] = v3;
            }
        }
    }
}

// =====================================================================
//  SIMT kernels
// =====================================================================
__device__ __forceinline__ float block_sum256(float v, float* red) {
    #pragma unroll
    for (int o = 16; o; o >>= 1) v += __shfl_down_sync(0xffffffffu, v, o);
    int lane = threadIdx.x & 31, wid = threadIdx.x >> 5;
    if (lane == 0) red[wid] = v;
    __syncthreads();
    if (wid == 0) {
        float w = (lane < 8) ? red[lane] : 0.f;
        #pragma unroll
        for (int o = 16; o; o >>= 1) w += __shfl_down_sync(0xffffffffu, w, o);
        if (lane == 0) red[0] = w;
    }
    __syncthreads();
    return red[0];
}

// rope (in place -> residual) + rmsnorm -> h hi/lo (bf16 split)
__global__ void __launch_bounds__(256)
rope_norm_kernel(float* __restrict__ q, bf16* __restrict__ hhi, bf16* __restrict__ hlo,
                 const float* __restrict__ w)
{
    int tok = blockIdx.x;
    int t = tok & (TSEQ - 1);
    __shared__ float row[DM];
    __shared__ float red[8];
    int tid = threadIdx.x;
    for (int i = tid; i < DM; i += 256) row[i] = q[(size_t)tok * DM + i];
    __syncthreads();

    float vals[4];
    float ss = 0.f;
    #pragma unroll
    for (int u = 0; u < 4; u++) {
        int d  = tid + u * 256;
        int hd = d & 63;
        int i  = hd & 31;
        float inv = exp2f(-(float)(2 * i) * (1.f / 64.f) * 13.287712379549449f);
        float ang = (float)t * inv;
        float c, s;
        sincosf(ang, &s, &c);
        float v;
        if (hd < 32) { float q1 = row[d], q2 = row[d + 32]; v = q1 * c - q2 * s; }
        else         { float q2 = row[d], q1 = row[d - 32]; v = q2 * c + q1 * s; }
        vals[u] = v;
        ss += v * v;
    }
    float total = block_sum256(ss, red);
    float scale = rsqrtf(total * (1.f / DM) + 1e-5f);
    #pragma unroll
    for (int u = 0; u < 4; u++) {
        int d = tid + u * 256;
        q[(size_t)tok * DM + d] = vals[u];
        float hv = vals[u] * scale * w[d];
        split1(hv, &hhi[(size_t)tok * DM + d], &hlo[(size_t)tok * DM + d]);
    }
}

__global__ void __launch_bounds__(256)
dt_kernel(const float* __restrict__ zx, const float* __restrict__ dtb,
          float* __restrict__ dt)
{
    int idx = blockIdx.x * blockDim.x + threadIdx.x;
    if (idx >= NTOK * HS) return;
    int tok = idx >> 5, hh = idx & 31;
    float x = zx[(size_t)tok * DIP + (DIP - HS) + hh] + dtb[hh];
    float sp = (x > 20.f) ? x : log1pf(expf(x));
    dt[idx] = sp;
}

// conv + silu; channels >= DINNER also emit bf16 hi/lo (B/C for the G gemm)
__global__ void __launch_bounds__(256)
conv_kernel(const float* __restrict__ zx, const float* __restrict__ cw,
            const float* __restrict__ cb, float* __restrict__ out,
            bf16* __restrict__ bchi, bf16* __restrict__ bclo)
{
    int idx = blockIdx.x * blockDim.x + threadIdx.x;
    if (idx >= NTOK * CONVD) return;
    int tok = idx / CONVD, ch = idx % CONVD;
    int t = tok & (TSEQ - 1);
    float acc = cb[ch];
    #pragma unroll
    for (int k = 0; k < 4; k++) {
        int tt = t + k - 3;
        if (tt >= 0) acc += zx[(size_t)(tok + k - 3) * DIP + DINNER + ch] * cw[ch * 4 + k];
    }
    float sg = 1.f / (1.f + expf(-acc));
    float v = acc * sg;
    out[(size_t)tok * CONVD + ch] = v;
    if (ch >= DINNER) {
        size_t o = (size_t)tok * 256 + (ch - DINNER);
        split1(v, &bchi[o], &bclo[o]);
    }
}

__global__ void __launch_bounds__(256)
ssd_part1(const float* __restrict__ xBC, const float* __restrict__ dt,
          const float* __restrict__ A_log, const float* __restrict__ G,
          float* __restrict__ y, float* __restrict__ states,
          float* __restrict__ Asum, float* __restrict__ expAcs)
{
    int h = blockIdx.x, c = blockIdx.y, b = blockIdx.z;
    int l = threadIdx.x;
    int tok0 = b * TSEQ + c * CH;

    __shared__ float sAcs[CH];
    __shared__ float sDt[CH];
    __shared__ float sDec[CH];
    __shared__ float sES[64];
    __shared__ float sX[64][64];
    __shared__ float warpsum[8];

    float dtl = dt[(size_t)(tok0 + l) * HS + h];
    float A   = -expf(A_log[h]);
    float adt = dtl * A;

    int lane = l & 31, wid = l >> 5;
    float v = adt;
    #pragma unroll
    for (int o = 1; o < 32; o <<= 1) {
        float u = __shfl_up_sync(0xffffffffu, v, o);
        if (lane >= o) v += u;
    }
    if (lane == 31) warpsum[wid] = v;
    __syncthreads();
    if (wid == 0) {
        float w = (lane < 8) ? warpsum[lane] : 0.f;
        #pragma unroll
        for (int o = 1; o < 8; o <<= 1) {
            float u = __shfl_up_sync(0xffffffffu, w, o);
            if (lane >= o) w += u;
        }
        if (lane < 8) warpsum[lane] = w;
    }
    __syncthreads();
    float acs   = v + ((wid > 0) ? warpsum[wid - 1] : 0.f);
    float total = warpsum[7];

    sAcs[l] = acs;
    sDt[l]  = dtl;
    sDec[l] = expf(total - acs);
    expAcs[(((size_t)(b * NC + c) * HS) + h) * CH + l] = expf(acs);
    if (l == 0) Asum[(b * HS + h) * NC + c] = total;
    __syncthreads();

    const float* Gp = G + ((size_t)(b * NC + c)) * CH * CH;

    float acc[64];
    #pragma unroll
    for (int p = 0; p < 64; p++) acc[p] = 0.f;

    for (int t4 = 0; t4 < 4; t4++) {
        int sbase = t4 * 64;
        __syncthreads();
        for (int i = l; i < 64 * 64; i += 256) {
            int r = i >> 6, cc2 = i & 63;
            sX[r][cc2] = xBC[(size_t)(tok0 + sbase + r) * CONVD + h * PD + cc2] * sDt[sbase + r];
        }
        if (l < 64) sES[l] = expf(sAcs[sbase + 63] - sAcs[sbase + l]);
        __syncthreads();

        if (sbase + 63 < l) {
            float f = expf(sAcs[l] - sAcs[sbase + 63]);
            for (int s = 0; s < 64; s++) {
                float w = Gp[(size_t)(sbase + s) * CH + l] * (f * sES[s]);
                const float4* xr = (const float4*)sX[s];
                #pragma unroll
                for (int p4 = 0; p4 < 16; p4++) {
                    float4 xx = xr[p4];
                    acc[p4 * 4 + 0] += w * xx.x;
                    acc[p4 * 4 + 1] += w * xx.y;
                    acc[p4 * 4 + 2] += w * xx.z;
                    acc[p4 * 4 + 3] += w * xx.w;
                }
            }
        } else if (sbase <= l) {
            for (int s = sbase; s <= l; s++) {
                float w = Gp[(size_t)s * CH + l] * expf(sAcs[l] - sAcs[s]);
                const float4* xr = (const float4*)sX[s - sbase];
                #pragma unroll
                for (int p4 = 0; p4 < 16; p4++) {
                    float4 xx = xr[p4];
                    acc[p4 * 4 + 0] += w * xx.x;
                    acc[p4 * 4 + 1] += w * xx.y;
                    acc[p4 * 4 + 2] += w * xx.z;
                    acc[p4 * 4 + 3] += w * xx.w;
                }
            }
        }
    }

    #pragma unroll
    for (int p = 0; p < 64; p++)
        y[(size_t)(tok0 + l) * DINNER + h * PD + p] = acc[p];
    __syncthreads();

    {
        int p  = l >> 2;
        int n0 = (l & 3) * 32;
        float st[32];
        #pragma unroll
        for (int i = 0; i < 32; i++) st[i] = 0.f;
        for (int ll = 0; ll < CH; ll++) {
            float coef = sDec[ll] * sDt[ll] * xBC[(size_t)(tok0 + ll) * CONVD + h * PD + p];
            const float4* bp = (const float4*)(xBC + (size_t)(tok0 + ll) * CONVD + DINNER + n0);
            #pragma unroll
            for (int j = 0; j < 8; j++) {
                float4 bb = bp[j];
                st[j * 4 + 0] += coef * bb.x;
                st[j * 4 + 1] += coef * bb.y;
                st[j * 4 + 2] += coef * bb.z;
                st[j * 4 + 3] += coef * bb.w;
            }
        }
        float* sp = states + (((size_t)(b * NC + c) * HS) + h) * PD * DS + (size_t)p * DS + n0;
        #pragma unroll
        for (int i = 0; i < 32; i++) sp[i] = st[i];
    }
}

__global__ void __launch_bounds__(256)
ssd_prefix(float* __restrict__ states, const float* __restrict__ Asum)
{
    int h = blockIdx.x, b = blockIdx.y;
    float dec[NC];
    #pragma unroll
    for (int c = 0; c < NC; c++) dec[c] = expf(Asum[(b * HS + h) * NC + c]);
    for (int idx = threadIdx.x; idx < PD * DS; idx += blockDim.x) {
        float S = 0.f;
        #pragma unroll
        for (int c = 0; c < NC; c++) {
            size_t off = (((size_t)(b * NC + c) * HS) + h) * PD * DS + idx;
            float st = states[off];
            states[off] = S;
            S = dec[c] * S + st;
        }
    }
}

__global__ void __launch_bounds__(256)
ssd_part2(const float* __restrict__ xBC, const float* __restrict__ statesPrev,
          const float* __restrict__ expAcs, const float* __restrict__ D_param,
          float* __restrict__ y)
{
    int h = blockIdx.x, c = blockIdx.y, b = blockIdx.z;
    int l = threadIdx.x;
    int tok0 = b * TSEQ + c * CH;

    __shared__ float sS[16][64];

    float acc[64];
    #pragma unroll
    for (int p = 0; p < 64; p++) acc[p] = 0.f;

    const float* Sp = statesPrev + (((size_t)(b * NC + c) * HS) + h) * PD * DS;
    const float* Crow = xBC + (size_t)(tok0 + l) * CONVD + DINNER + DS;

    for (int nt = 0; nt < 8; nt++) {
        int n0 = nt * 16;
        float cre[16];
        {
            const float4* cp = (const float4*)(Crow + n0);
            #pragma unroll
            for (int q4 = 0; q4 < 4; q4++) {
                float4 vv = cp[q4];
                cre[q4 * 4 + 0] = vv.x; cre[q4 * 4 + 1] = vv.y;
                cre[q4 * 4 + 2] = vv.z; cre[q4 * 4 + 3] = vv.w;
            }
        }
        __syncthreads();
        for (int i = l; i < 16 * 64; i += 256) {
            int nn = i & 15, p = i >> 4;
            sS[nn][p] = Sp[(size_t)p * DS + n0 + nn];
        }
        __syncthreads();
        #pragma unroll
        for (int nn = 0; nn < 16; nn++) {
            float cv = cre[nn];
            const float4* sr = (const float4*)sS[nn];
            #pragma unroll
            for (int p4 = 0; p4 < 16; p4++) {
                float4 sv = sr[p4];
                acc[p4 * 4 + 0] += cv * sv.x;
                acc[p4 * 4 + 1] += cv * sv.y;
                acc[p4 * 4 + 2] += cv * sv.z;
                acc[p4 * 4 + 3] += cv * sv.w;
            }
        }
    }

    float eA = expAcs[(((size_t)(b * NC + c) * HS) + h) * CH + l];
    float Dp = D_param[h];
    size_t ybase = (size_t)(tok0 + l) * DINNER + h * PD;
    size_t xbase = (size_t)(tok0 + l) * CONVD + h * PD;
    #pragma unroll
    for (int p = 0; p < 64; p++) {
        float xv = xBC[xbase + p];
        y[ybase + p] = y[ybase + p] + eA * acc[p] + Dp * xv;
    }
}

// gated rmsnorm -> yg hi/lo (bf16 split)
__global__ void __launch_bounds__(256)
gate_norm_kernel(const float* __restrict__ y, const float* __restrict__ zx,
                 const float* __restrict__ w, bf16* __restrict__ yghi,
                 bf16* __restrict__ yglo)
{
    int tok = blockIdx.x, tid = threadIdx.x;
    __shared__ float red[8];
    float g[8];
    float ss = 0.f;
    #pragma unroll
    for (int u = 0; u < 8; u++) {
        int d = tid + u * 256;
        float z  = zx[(size_t)tok * DIP + d];
        float yy = y[(size_t)tok * DINNER + d];
        float gv = yy * (z / (1.f + expf(-z)));
        g[u] = gv;
        ss += gv * gv;
    }
    float total = block_sum256(ss, red);
    float sc = rsqrtf(total * (1.f / DINNER) + 1e-5f);
    #pragma unroll
    for (int u = 0; u < 8; u++) {
        int d = tid + u * 256;
        float v = g[u] * sc * w[d];
        split1(v, &yghi[(size_t)tok * DINNER + d], &yglo[(size_t)tok * DINNER + d]);
    }
}

// ---------------- launch ----------------
extern "C" void kernel_launch(void* const* d_in, const int* in_sizes, int n_in,
                              void* d_out, int out_size)
{
    const float* x         = (const float*)d_in[0];
    const float* W_in      = (const float*)d_in[1];
    const float* W_z       = (const float*)d_in[2];
    const float* conv_w    = (const float*)d_in[3];
    const float* conv_b    = (const float*)d_in[4];
    const float* dt_bias   = (const float*)d_in[5];
    const float* A_log     = (const float*)d_in[6];
    const float* D_param   = (const float*)d_in[7];
    const float* norm_pre  = (const float*)d_in[8];
    const float* norm_gate = (const float*)d_in[9];
    const float* W_out     = (const float*)d_in[10];
    float* out = (float*)d_out;

    float* sc = nullptr;
    cudaGetSymbolAddress((void**)&sc, g_scratch);
    bf16* XHI = (bf16*)(sc + OFF_XHI); bf16* XLO = (bf16*)(sc + OFF_XLO);
    bf16* WIH = (bf16*)(sc + OFF_WIH); bf16* WIL = (bf16*)(sc + OFF_WIL);
    bf16* WZH = (bf16*)(sc + OFF_WZH); bf16* WZL = (bf16*)(sc + OFF_WZL);
    bf16* WOH = (bf16*)(sc + OFF_WOH); bf16* WOL = (bf16*)(sc + OFF_WOL);
    bf16* HH  = (bf16*)(sc + OFF_HH);  bf16* HL  = (bf16*)(sc + OFF_HL);
    bf16* YGH = (bf16*)(sc + OFF_YGH); bf16* YGL = (bf16*)(sc + OFF_YGL);
    bf16* BCH = (bf16*)(sc + OFF_BCH); bf16* BCL = (bf16*)(sc + OFF_BCL);

    cudaFuncSetAttribute(gemm_bf3, cudaFuncAttributeMaxDynamicSharedMemorySize, GEMM_SMEM);

    // 0) operand pre-splits
    cvt_split<<<(NTOK * DM / 4 + 255) / 256, 256>>>(x, XHI, XLO, NTOK * DM / 4);
    cvt_split<<<(DM * DM / 4 + 255) / 256, 256>>>(W_in, WIH, WIL, DM * DM / 4);      // q rows only
    cvt_split<<<(DIP * DM / 4 + 255) / 256, 256>>>(W_z, WZH, WZL, DIP * DM / 4);
    cvt_split<<<(DM * DINNER / 4 + 255) / 256, 256>>>(W_out, WOH, WOL, DM * DINNER / 4);

    // 1) q = x @ W_in[:1024].T
    gemm_bf3<<<dim3(DM / BN, NTOK / BM, 1), 256, GEMM_SMEM>>>(
        XHI, XLO, WIH, WIL, sc + OFF_Q, nullptr, NTOK, DM, DM, DM, DM, DM, 0, 0, 0);

    // 2) rope (in place -> residual) + rmsnorm -> h hi/lo
    rope_norm_kernel<<<NTOK, 256>>>(sc + OFF_Q, HH, HL, norm_pre);

    // 3) zxbcdt = h @ W_zxbcdt.T
    gemm_bf3<<<dim3((DIP + BN - 1) / BN, NTOK / BM, 1), 256, GEMM_SMEM>>>(
        HH, HL, WZH, WZL, sc + OFF_ZX, nullptr, NTOK, DIP, DM, DM, DM, DIP, 0, 0, 0);

    // 4) dt
    dt_kernel<<<(NTOK * HS + 255) / 256, 256>>>(sc + OFF_ZX, dt_bias, sc + OFF_DT);

    // 5) conv + silu (+ B/C hi/lo emission)
    conv_kernel<<<(NTOK * CONVD + 255) / 256, 256>>>(sc + OFF_ZX, conv_w, conv_b,
                                                     sc + OFF_XBC, BCH, BCL);

    // 6) G^T[s][l] = B_s . C_l, batched over 16 chunks
    gemm_bf3<<<dim3(CH / BN, CH / BM, 16), 256, GEMM_SMEM>>>(
        BCH, BCL, BCH + DS, BCL + DS, sc + OFF_G, nullptr,
        CH, CH, DS, 256, 256, CH,
        (size_t)CH * 256, (size_t)CH * 256, (size_t)CH * CH);

    // 7) SSD: Y_diag + chunk states
    ssd_part1<<<dim3(HS, NC, 2), 256>>>(
        sc + OFF_XBC, sc + OFF_DT, A_log, sc + OFF_G,
        sc + OFF_Y, sc + OFF_ST, sc + OFF_ASUM, sc + OFF_EACS);

    // 8) cross-chunk prefix
    ssd_prefix<<<dim3(HS, 2), 256>>>(sc + OFF_ST, sc + OFF_ASUM);

    // 9) Y += exp(Acs) * (C . S_prev) + D * x
    ssd_part2<<<dim3(HS, NC, 2), 256>>>(
        sc + OFF_XBC, sc + OFF_ST, sc + OFF_EACS, D_param, sc + OFF_Y);

    // 10) gated rmsnorm -> yg hi/lo
    gate_norm_kernel<<<NTOK, 256>>>(sc + OFF_Y, sc + OFF_ZX, norm_gate, YGH, YGL);

    // 11) out = yg @ W_out.T + residual
    gemm_bf3<<<dim3(DM / BN, NTOK / BM, 1), 256, GEMM_SMEM>>>(
        YGH, YGL, WOH, WOL, out, sc + OFF_Q, NTOK, DM, DINNER, DINNER, DINNER, DM, 0, 0, 0);
}

// round 6
// speedup vs baseline: 1.9670x; 1.1222x over previous
#include <cuda_runtime.h>
#include <cuda_fp16.h>
#include <math.h>
#include <stdint.h>

// ---------------- problem constants ----------------
#define NTOK   4096          // N*T = 2*2048
#define TSEQ   2048
#define DM     1024          // d_model
#define DIP    4384          // d_in_proj
#define DINNER 2048
#define CONVD  2304          // d_inner + 2*d_state
#define HS     32            // ssm heads
#define PD     64            // headdim
#define DS     128           // d_state
#define CH     256           // chunk
#define NC     8             // chunks per sequence

// ---------------- scratch layout (floats) ----------------
#define OFF_Q    0ull                 // 4096*1024   roped q (residual)
#define OFF_ZX   8388608ull           // 4096*4384   zxbcdt
#define OFF_XBC  26345472ull          // 4096*2304   conv+silu output
#define OFF_DT   35782656ull          // 4096*32     softplus dt
#define OFF_G    35913728ull          // 16*256*256  G^T per (b,c): [s][l]
#define OFF_ST   36962304ull          // 16*32*64*128 chunk states -> states_prev
#define OFF_ASUM 41156608ull          // 2*32*8      chunk A sums
#define OFF_EACS 41157120ull          // 16*32*256   exp(Acs)
#define OFF_Y    41288192ull          // 4096*2048   y
// fp16 arrays (offsets in floats; 1 float = 2 halves)
#define OFF_XHI  58065408ull
#define OFF_XLO  60162560ull
#define OFF_WIH  62259712ull
#define OFF_WZH  63308288ull
#define OFF_WOH  67797504ull
#define OFF_HH   69894656ull
#define OFF_HL   71991808ull
#define OFF_YGH  74088960ull
#define OFF_YGL  78283264ull
#define OFF_BCH  82477568ull
#define OFF_BCL  83001856ull
#define SCRATCH_FLOATS 83526144ull

__device__ float g_scratch[SCRATCH_FLOATS];

typedef __half hf;

// =====================================================================
//  helpers
// =====================================================================
__device__ __forceinline__ uint32_t sm32(const void* p) {
    return (uint32_t)__cvta_generic_to_shared(p);
}
__device__ __forceinline__ void ldsm_x4(uint32_t& r0, uint32_t& r1, uint32_t& r2, uint32_t& r3,
                                        uint32_t a) {
    asm volatile("ldmatrix.sync.aligned.m8n8.x4.shared.b16 {%0,%1,%2,%3}, [%4];"
                 : "=r"(r0), "=r"(r1), "=r"(r2), "=r"(r3) : "r"(a));
}
__device__ __forceinline__ void ldsm_x2(uint32_t& r0, uint32_t& r1, uint32_t a) {
    asm volatile("ldmatrix.sync.aligned.m8n8.x2.shared.b16 {%0,%1}, [%2];"
                 : "=r"(r0), "=r"(r1) : "r"(a));
}
__device__ __forceinline__ void mma16816h(float* c, const uint32_t* a, uint32_t b0, uint32_t b1) {
    asm volatile(
        "mma.sync.aligned.m16n8k16.row.col.f32.f16.f16.f32 "
        "{%0,%1,%2,%3}, {%4,%5,%6,%7}, {%8,%9}, {%0,%1,%2,%3};"
        : "+f"(c[0]), "+f"(c[1]), "+f"(c[2]), "+f"(c[3])
        : "r"(a[0]), "r"(a[1]), "r"(a[2]), "r"(a[3]), "r"(b0), "r"(b1));
}
__device__ __forceinline__ void split1h(float x, hf* hi, hf* lo) {
    hf h = __float2half_rn(x);
    *hi = h;
    *lo = __float2half_rn(x - __half2float(h));
}
__device__ __forceinline__ void cp16(uint32_t s, const void* g, int bytes) {
    asm volatile("cp.async.cg.shared.global [%0], [%1], 16, %2;"
                 :: "r"(s), "l"(g), "r"(bytes));
}

// fp32 -> fp16 hi+lo (for A-side activations)
__global__ void __launch_bounds__(256)
cvt_split(const float* __restrict__ in, hf* __restrict__ hi, hf* __restrict__ lo, int n4)
{
    int i = blockIdx.x * blockDim.x + threadIdx.x;
    if (i >= n4) return;
    float4 v = ((const float4*)in)[i];
    hf h[4], l[4];
    split1h(v.x, &h[0], &l[0]);
    split1h(v.y, &h[1], &l[1]);
    split1h(v.z, &h[2], &l[2]);
    split1h(v.w, &h[3], &l[3]);
    ((uint2*)hi)[i] = *(uint2*)h;
    ((uint2*)lo)[i] = *(uint2*)l;
}
// fp32 -> fp16 hi only (for B-side weights)
__global__ void __launch_bounds__(256)
cvt_hi(const float* __restrict__ in, hf* __restrict__ hi, int n4)
{
    int i = blockIdx.x * blockDim.x + threadIdx.x;
    if (i >= n4) return;
    float4 v = ((const float4*)in)[i];
    hf h[4];
    h[0] = __float2half_rn(v.x); h[1] = __float2half_rn(v.y);
    h[2] = __float2half_rn(v.z); h[3] = __float2half_rn(v.w);
    ((uint2*)hi)[i] = *(uint2*)h;
}

// =====================================================================
//  pipelined fp16 2-product GEMM: C = (Ahi+Alo)(MxK) * Bhi(NxK)^T (+addC)
//  128x128 tile, BK=32, 256 threads = 8 warps (4 x 2), warp = 32x64
// =====================================================================
#define BM 128
#define BN 128
#define BK 32
#define LDK 40                // halves per smem row (80 B; first 32 real)
#define MAT  (BM * LDK)       // 5120 halves per matrix
#define STG  (3 * MAT)        // Ah, Al, Bh
#define GEMM_SMEM (2 * STG * 2)   // bytes (2 stages)

__global__ void __launch_bounds__(256)
gemm_hf2(const hf* __restrict__ Ahi, const hf* __restrict__ Alo,
         const hf* __restrict__ Bhi,
         float* __restrict__ C, const float* __restrict__ addC,
         int M, int N, int K, int lda, int ldb, int ldc,
         size_t bsA, size_t bsB, size_t bsC)
{
    extern __shared__ hf sm[];

    Ahi += bsA * blockIdx.z; Alo += bsA * blockIdx.z;
    Bhi += bsB * blockIdx.z;
    C   += bsC * blockIdx.z;

    int tid = threadIdx.x, lane = tid & 31, wid = tid >> 5;
    int warp_m = wid & 3, warp_n = wid >> 2;
    int m0 = blockIdx.y * BM, n0 = blockIdx.x * BN;

    float acc[2][8][4];
    #pragma unroll
    for (int mt = 0; mt < 2; mt++)
        #pragma unroll
        for (int nt = 0; nt < 8; nt++)
            #pragma unroll
            for (int e = 0; e < 4; e++) acc[mt][nt][e] = 0.f;

    const int KC = K >> 5;

    int r0 = tid >> 2,         k80 = (tid & 3) << 3;
    int r1 = (tid + 256) >> 2;
    bool bv0 = (n0 + r0) < N, bv1 = (n0 + r1) < N;
    int br0 = bv0 ? r0 : 0, br1 = bv1 ? r1 : 0;

    auto load_stage = [&](int kc, int st) {
        hf* base = sm + st * STG;
        uint32_t s0 = sm32(base + r0 * LDK + k80);
        uint32_t s1 = sm32(base + r1 * LDK + k80);
        size_t a0 = (size_t)(m0 + r0) * lda + kc + k80;
        size_t a1 = (size_t)(m0 + r1) * lda + kc + k80;
        size_t b0 = (size_t)(n0 + br0) * ldb + kc + k80;
        size_t b1 = (size_t)(n0 + br1) * ldb + kc + k80;
        cp16(s0,               Ahi + a0, 16);
        cp16(s1,               Ahi + a1, 16);
        cp16(s0 + 2 * MAT,     Alo + a0, 16);
        cp16(s1 + 2 * MAT,     Alo + a1, 16);
        cp16(s0 + 4 * MAT,     Bhi + b0, bv0 ? 16 : 0);
        cp16(s1 + 4 * MAT,     Bhi + b1, bv1 ? 16 : 0);
    };

    int a_r = (lane & 15), a_k = ((lane >> 4) << 3);
    int b_r = (lane & 7),  b_k = (((lane >> 3) & 1) << 3);

    load_stage(0, 0);
    asm volatile("cp.async.commit_group;");

    for (int c = 0; c < KC; c++) {
        if (c + 1 < KC) {
            load_stage((c + 1) << 5, (c + 1) & 1);
            asm volatile("cp.async.commit_group;");
            asm volatile("cp.async.wait_group 1;");
        } else {
            asm volatile("cp.async.wait_group 0;");
        }
        __syncthreads();

        hf* base = sm + (c & 1) * STG;
        hf* sAh = base;
        hf* sAl = base + MAT;
        hf* sBh = base + 2 * MAT;

        #pragma unroll
        for (int ks = 0; ks < 2; ks++) {
            int k0 = ks * 16;
            uint32_t ah[2][4], al[2][4];
            #pragma unroll
            for (int mt = 0; mt < 2; mt++) {
                int ar = (warp_m * 32 + mt * 16 + a_r) * LDK + k0 + a_k;
                ldsm_x4(ah[mt][0], ah[mt][1], ah[mt][2], ah[mt][3], sm32(&sAh[ar]));
                ldsm_x4(al[mt][0], al[mt][1], al[mt][2], al[mt][3], sm32(&sAl[ar]));
            }
            #pragma unroll
            for (int nt = 0; nt < 8; nt++) {
                int br = (warp_n * 64 + nt * 8 + b_r) * LDK + k0 + b_k;
                uint32_t bh0, bh1;
                ldsm_x2(bh0, bh1, sm32(&sBh[br]));
                #pragma unroll
                for (int mt = 0; mt < 2; mt++) {
                    mma16816h(acc[mt][nt], ah[mt], bh0, bh1);   // hi*hi
                    mma16816h(acc[mt][nt], al[mt], bh0, bh1);   // lo*hi
                }
            }
        }
        __syncthreads();
    }

    int tg = lane >> 2, tq = lane & 3;
    #pragma unroll
    for (int mt = 0; mt < 2; mt++) {
        int m = m0 + warp_m * 32 + mt * 16 + tg;
        #pragma unroll
        for (int nt = 0; nt < 8; nt++) {
            int n = n0 + warp_n * 64 + nt * 8 + tq * 2;
            if (n < N) {
                size_t o0 = (size_t)m * ldc + n;
                size_t o1 = (size_t)(m + 8) * ldc + n;
                float v0 = acc[mt][nt][0], v1 = acc[mt][nt][1];
                float v2 = acc[mt][nt][2], v3 = acc[mt][nt][3];
                if (addC) {
                    v0 += addC[o0]; v1 += addC[o0 + 1];
                    v2 += addC[o1]; v3 += addC[o1 + 1];
                }
                C[o0] = v0; C[o0 + 1] = v1;
                C[o1] = v2; C[o1 + 1] = v3;
            }
        }
    }
}

// =====================================================================
//  SIMT kernels
// =====================================================================
__device__ __forceinline__ float block_sum256(float v, float* red) {
    #pragma unroll
    for (int o = 16; o; o >>= 1) v += __shfl_down_sync(0xffffffffu, v, o);
    int lane = threadIdx.x & 31, wid = threadIdx.x >> 5;
    if (lane == 0) red[wid] = v;
    __syncthreads();
    if (wid == 0) {
        float w = (lane < 8) ? red[lane] : 0.f;
        #pragma unroll
        for (int o = 16; o; o >>= 1) w += __shfl_down_sync(0xffffffffu, w, o);
        if (lane == 0) red[0] = w;
    }
    __syncthreads();
    return red[0];
}

// rope (in place -> residual) + rmsnorm -> h hi/lo (fp16 split)
__global__ void __launch_bounds__(256)
rope_norm_kernel(float* __restrict__ q, hf* __restrict__ hhi, hf* __restrict__ hlo,
                 const float* __restrict__ w)
{
    int tok = blockIdx.x;
    int t = tok & (TSEQ - 1);
    __shared__ float row[DM];
    __shared__ float red[8];
    int tid = threadIdx.x;
    for (int i = tid; i < DM; i += 256) row[i] = q[(size_t)tok * DM + i];
    __syncthreads();

    float vals[4];
    float ss = 0.f;
    #pragma unroll
    for (int u = 0; u < 4; u++) {
        int d  = tid + u * 256;
        int hd = d & 63;
        int i  = hd & 31;
        float inv = exp2f(-(float)(2 * i) * (1.f / 64.f) * 13.287712379549449f);
        float ang = (float)t * inv;
        float c, s;
        sincosf(ang, &s, &c);
        float v;
        if (hd < 32) { float q1 = row[d], q2 = row[d + 32]; v = q1 * c - q2 * s; }
        else         { float q2 = row[d], q1 = row[d - 32]; v = q2 * c + q1 * s; }
        vals[u] = v;
        ss += v * v;
    }
    float total = block_sum256(ss, red);
    float scale = rsqrtf(total * (1.f / DM) + 1e-5f);
    #pragma unroll
    for (int u = 0; u < 4; u++) {
        int d = tid + u * 256;
        q[(size_t)tok * DM + d] = vals[u];
        float hv = vals[u] * scale * w[d];
        split1h(hv, &hhi[(size_t)tok * DM + d], &hlo[(size_t)tok * DM + d]);
    }
}

__global__ void __launch_bounds__(256)
dt_kernel(const float* __restrict__ zx, const float* __restrict__ dtb,
          float* __restrict__ dt)
{
    int idx = blockIdx.x * blockDim.x + threadIdx.x;
    if (idx >= NTOK * HS) return;
    int tok = idx >> 5, hh = idx & 31;
    float x = zx[(size_t)tok * DIP + (DIP - HS) + hh] + dtb[hh];
    float sp = (x > 20.f) ? x : log1pf(expf(x));
    dt[idx] = sp;
}

// conv + silu; channels >= DINNER also emit fp16 hi/lo (B/C for the G gemm)
__global__ void __launch_bounds__(256)
conv_kernel(const float* __restrict__ zx, const float* __restrict__ cw,
            const float* __restrict__ cb, float* __restrict__ out,
            hf* __restrict__ bchi, hf* __restrict__ bclo)
{
    int idx = blockIdx.x * blockDim.x + threadIdx.x;
    if (idx >= NTOK * CONVD) return;
    int tok = idx / CONVD, ch = idx % CONVD;
    int t = tok & (TSEQ - 1);
    float acc = cb[ch];
    #pragma unroll
    for (int k = 0; k < 4; k++) {
        int tt = t + k - 3;
        if (tt >= 0) acc += zx[(size_t)(tok + k - 3) * DIP + DINNER + ch] * cw[ch * 4 + k];
    }
    float sg = 1.f / (1.f + expf(-acc));
    float v = acc * sg;
    out[(size_t)tok * CONVD + ch] = v;
    if (ch >= DINNER) {
        size_t o = (size_t)tok * 256 + (ch - DINNER);
        split1h(v, &bchi[o], &bclo[o]);
    }
}

__global__ void __launch_bounds__(256)
ssd_part1(const float* __restrict__ xBC, const float* __restrict__ dt,
          const float* __restrict__ A_log, const float* __restrict__ G,
          float* __restrict__ y, float* __restrict__ states,
          float* __restrict__ Asum, float* __restrict__ expAcs)
{
    int h = blockIdx.x, c = blockIdx.y, b = blockIdx.z;
    int l = threadIdx.x;
    int tok0 = b * TSEQ + c * CH;

    __shared__ float sAcs[CH];
    __shared__ float sDt[CH];
    __shared__ float sDec[CH];
    __shared__ float sES[64];
    __shared__ float sX[64][64];
    __shared__ float warpsum[8];

    float dtl = dt[(size_t)(tok0 + l) * HS + h];
    float A   = -expf(A_log[h]);
    float adt = dtl * A;

    int lane = l & 31, wid = l >> 5;
    float v = adt;
    #pragma unroll
    for (int o = 1; o < 32; o <<= 1) {
        float u = __shfl_up_sync(0xffffffffu, v, o);
        if (lane >= o) v += u;
    }
    if (lane == 31) warpsum[wid] = v;
    __syncthreads();
    if (wid == 0) {
        float w = (lane < 8) ? warpsum[lane] : 0.f;
        #pragma unroll
        for (int o = 1; o < 8; o <<= 1) {
            float u = __shfl_up_sync(0xffffffffu, w, o);
            if (lane >= o) w += u;
        }
        if (lane < 8) warpsum[lane] = w;
    }
    __syncthreads();
    float acs   = v + ((wid > 0) ? warpsum[wid - 1] : 0.f);
    float total = warpsum[7];

    sAcs[l] = acs;
    sDt[l]  = dtl;
    sDec[l] = expf(total - acs);
    expAcs[(((size_t)(b * NC + c) * HS) + h) * CH + l] = expf(acs);
    if (l == 0) Asum[(b * HS + h) * NC + c] = total;
    __syncthreads();

    const float* Gp = G + ((size_t)(b * NC + c)) * CH * CH;

    float acc[64];
    #pragma unroll
    for (int p = 0; p < 64; p++) acc[p] = 0.f;

    for (int t4 = 0; t4 < 4; t4++) {
        int sbase = t4 * 64;
        __syncthreads();
        for (int i = l; i < 64 * 64; i += 256) {
            int r = i >> 6, cc2 = i & 63;
            sX[r][cc2] = xBC[(size_t)(tok0 + sbase + r) * CONVD + h * PD + cc2] * sDt[sbase + r];
        }
        if (l < 64) sES[l] = expf(sAcs[sbase + 63] - sAcs[sbase + l]);
        __syncthreads();

        if (sbase + 63 < l) {
            float f = expf(sAcs[l] - sAcs[sbase + 63]);
            for (int s = 0; s < 64; s++) {
                float w = Gp[(size_t)(sbase + s) * CH + l] * (f * sES[s]);
                const float4* xr = (const float4*)sX[s];
                #pragma unroll
                for (int p4 = 0; p4 < 16; p4++) {
                    float4 xx = xr[p4];
                    acc[p4 * 4 + 0] += w * xx.x;
                    acc[p4 * 4 + 1] += w * xx.y;
                    acc[p4 * 4 + 2] += w * xx.z;
                    acc[p4 * 4 + 3] += w * xx.w;
                }
            }
        } else if (sbase <= l) {
            for (int s = sbase; s <= l; s++) {
                float w = Gp[(size_t)s * CH + l] * expf(sAcs[l] - sAcs[s]);
                const float4* xr = (const float4*)sX[s - sbase];
                #pragma unroll
                for (int p4 = 0; p4 < 16; p4++) {
                    float4 xx = xr[p4];
                    acc[p4 * 4 + 0] += w * xx.x;
                    acc[p4 * 4 + 1] += w * xx.y;
                    acc[p4 * 4 + 2] += w * xx.z;
                    acc[p4 * 4 + 3] += w * xx.w;
                }
            }
        }
    }

    #pragma unroll
    for (int p = 0; p < 64; p++)
        y[(size_t)(tok0 + l) * DINNER + h * PD + p] = acc[p];
    __syncthreads();

    {
        int p  = l >> 2;
        int n0 = (l & 3) * 32;
        float st[32];
        #pragma unroll
        for (int i = 0; i < 32; i++) st[i] = 0.f;
        for (int ll = 0; ll < CH; ll++) {
            float coef = sDec[ll] * sDt[ll] * xBC[(size_t)(tok0 + ll) * CONVD + h * PD + p];
            const float4* bp = (const float4*)(xBC + (size_t)(tok0 + ll) * CONVD + DINNER + n0);
            #pragma unroll
            for (int j = 0; j < 8; j++) {
                float4 bb = bp[j];
                st[j * 4 + 0] += coef * bb.x;
                st[j * 4 + 1] += coef * bb.y;
                st[j * 4 + 2] += coef * bb.z;
                st[j * 4 + 3] += coef * bb.w;
            }
        }
        float* sp = states + (((size_t)(b * NC + c) * HS) + h) * PD * DS + (size_t)p * DS + n0;
        #pragma unroll
        for (int i = 0; i < 32; i++) sp[i] = st[i];
    }
}

__global__ void __launch_bounds__(256)
ssd_prefix(float* __restrict__ states, const float* __restrict__ Asum)
{
    int h = blockIdx.x, b = blockIdx.y;
    float dec[NC];
    #pragma unroll
    for (int c = 0; c < NC; c++) dec[c] = expf(Asum[(b * HS + h) * NC + c]);
    for (int idx = threadIdx.x; idx < PD * DS; idx += blockDim.x) {
        float S = 0.f;
        #pragma unroll
        for (int c = 0; c < NC; c++) {
            size_t off = (((size_t)(b * NC + c) * HS) + h) * PD * DS + idx;
            float st = states[off];
            states[off] = S;
            S = dec[c] * S + st;
        }
    }
}

__global__ void __launch_bounds__(256)
ssd_part2(const float* __restrict__ xBC, const float* __restrict__ statesPrev,
          const float* __restrict__ expAcs, const float* __restrict__ D_param,
          float* __restrict__ y)
{
    int h = blockIdx.x, c = blockIdx.y, b = blockIdx.z;
    int l = threadIdx.x;
    int tok0 = b * TSEQ + c * CH;

    __shared__ float sS[16][64];

    float acc[64];
    #pragma unroll
    for (int p = 0; p < 64; p++) acc[p] = 0.f;

    const float* Sp = statesPrev + (((size_t)(b * NC + c) * HS) + h) * PD * DS;
    const float* Crow = xBC + (size_t)(tok0 + l) * CONVD + DINNER + DS;

    for (int nt = 0; nt < 8; nt++) {
        int n0 = nt * 16;
        float cre[16];
        {
            const float4* cp = (const float4*)(Crow + n0);
            #pragma unroll
            for (int q4 = 0; q4 < 4; q4++) {
                float4 vv = cp[q4];
                cre[q4 * 4 + 0] = vv.x; cre[q4 * 4 + 1] = vv.y;
                cre[q4 * 4 + 2] = vv.z; cre[q4 * 4 + 3] = vv.w;
            }
        }
        __syncthreads();
        for (int i = l; i < 16 * 64; i += 256) {
            int nn = i & 15, p = i >> 4;
            sS[nn][p] = Sp[(size_t)p * DS + n0 + nn];
        }
        __syncthreads();
        #pragma unroll
        for (int nn = 0; nn < 16; nn++) {
            float cv = cre[nn];
            const float4* sr = (const float4*)sS[nn];
            #pragma unroll
            for (int p4 = 0; p4 < 16; p4++) {
                float4 sv = sr[p4];
                acc[p4 * 4 + 0] += cv * sv.x;
                acc[p4 * 4 + 1] += cv * sv.y;
                acc[p4 * 4 + 2] += cv * sv.z;
                acc[p4 * 4 + 3] += cv * sv.w;
            }
        }
    }

    float eA = expAcs[(((size_t)(b * NC + c) * HS) + h) * CH + l];
    float Dp = D_param[h];
    size_t ybase = (size_t)(tok0 + l) * DINNER + h * PD;
    size_t xbase = (size_t)(tok0 + l) * CONVD + h * PD;
    #pragma unroll
    for (int p = 0; p < 64; p++) {
        float xv = xBC[xbase + p];
        y[ybase + p] = y[ybase + p] + eA * acc[p] + Dp * xv;
    }
}

// gated rmsnorm -> yg hi/lo (fp16 split)
__global__ void __launch_bounds__(256)
gate_norm_kernel(const float* __restrict__ y, const float* __restrict__ zx,
                 const float* __restrict__ w, hf* __restrict__ yghi,
                 hf* __restrict__ yglo)
{
    int tok = blockIdx.x, tid = threadIdx.x;
    __shared__ float red[8];
    float g[8];
    float ss = 0.f;
    #pragma unroll
    for (int u = 0; u < 8; u++) {
        int d = tid + u * 256;
        float z  = zx[(size_t)tok * DIP + d];
        float yy = y[(size_t)tok * DINNER + d];
        float gv = yy * (z / (1.f + expf(-z)));
        g[u] = gv;
        ss += gv * gv;
    }
    float total = block_sum256(ss, red);
    float sc = rsqrtf(total * (1.f / DINNER) + 1e-5f);
    #pragma unroll
    for (int u = 0; u < 8; u++) {
        int d = tid + u * 256;
        float v = g[u] * sc * w[d];
        split1h(v, &yghi[(size_t)tok * DINNER + d], &yglo[(size_t)tok * DINNER + d]);
    }
}

// ---------------- launch ----------------
extern "C" void kernel_launch(void* const* d_in, const int* in_sizes, int n_in,
                              void* d_out, int out_size)
{
    const float* x         = (const float*)d_in[0];
    const float* W_in      = (const float*)d_in[1];
    const float* W_z       = (const float*)d_in[2];
    const float* conv_w    = (const float*)d_in[3];
    const float* conv_b    = (const float*)d_in[4];
    const float* dt_bias   = (const float*)d_in[5];
    const float* A_log     = (const float*)d_in[6];
    const float* D_param   = (const float*)d_in[7];
    const float* norm_pre  = (const float*)d_in[8];
    const float* norm_gate = (const float*)d_in[9];
    const float* W_out     = (const float*)d_in[10];
    float* out = (float*)d_out;

    float* sc = nullptr;
    cudaGetSymbolAddress((void**)&sc, g_scratch);
    hf* XHI = (hf*)(sc + OFF_XHI); hf* XLO = (hf*)(sc + OFF_XLO);
    hf* WIH = (hf*)(sc + OFF_WIH);
    hf* WZH = (hf*)(sc + OFF_WZH);
    hf* WOH = (hf*)(sc + OFF_WOH);
    hf* HH  = (hf*)(sc + OFF_HH);  hf* HL  = (hf*)(sc + OFF_HL);
    hf* YGH = (hf*)(sc + OFF_YGH); hf* YGL = (hf*)(sc + OFF_YGL);
    hf* BCH = (hf*)(sc + OFF_BCH); hf* BCL = (hf*)(sc + OFF_BCL);

    cudaFuncSetAttribute(gemm_hf2, cudaFuncAttributeMaxDynamicSharedMemorySize, GEMM_SMEM);

    // 0) operand pre-conversions
    cvt_split<<<(NTOK * DM / 4 + 255) / 256, 256>>>(x, XHI, XLO, NTOK * DM / 4);
    cvt_hi<<<(DM * DM / 4 + 255) / 256, 256>>>(W_in, WIH, DM * DM / 4);   // q rows only
    cvt_hi<<<(DIP * DM / 4 + 255) / 256, 256>>>(W_z, WZH, DIP * DM / 4);
    cvt_hi<<<(DM * DINNER / 4 + 255) / 256, 256>>>(W_out, WOH, DM * DINNER / 4);

    // 1) q = x @ W_in[:1024].T
    gemm_hf2<<<dim3(DM / BN, NTOK / BM, 1), 256, GEMM_SMEM>>>(
        XHI, XLO, WIH, sc + OFF_Q, nullptr, NTOK, DM, DM, DM, DM, DM, 0, 0, 0);

    // 2) rope (in place -> residual) + rmsnorm -> h hi/lo
    rope_norm_kernel<<<NTOK, 256>>>(sc + OFF_Q, HH, HL, norm_pre);

    // 3) zxbcdt = h @ W_zxbcdt.T
    gemm_hf2<<<dim3((DIP + BN - 1) / BN, NTOK / BM, 1), 256, GEMM_SMEM>>>(
        HH, HL, WZH, sc + OFF_ZX, nullptr, NTOK, DIP, DM, DM, DM, DIP, 0, 0, 0);

    // 4) dt
    dt_kernel<<<(NTOK * HS + 255) / 256, 256>>>(sc + OFF_ZX, dt_bias, sc + OFF_DT);

    // 5) conv + silu (+ B/C fp16 emission)
    conv_kernel<<<(NTOK * CONVD + 255) / 256, 256>>>(sc + OFF_ZX, conv_w, conv_b,
                                                     sc + OFF_XBC, BCH, BCL);

    // 6) G^T[s][l] = B_s . C_l, batched over 16 chunks
    gemm_hf2<<<dim3(CH / BN, CH / BM, 16), 256, GEMM_SMEM>>>(
        BCH, BCL, BCH + DS, sc + OFF_G, nullptr,
        CH, CH, DS, 256, 256, CH,
        (size_t)CH * 256, (size_t)CH * 256, (size_t)CH * CH);

    // 7) SSD: Y_diag + chunk states
    ssd_part1<<<dim3(HS, NC, 2), 256>>>(
        sc + OFF_XBC, sc + OFF_DT, A_log, sc + OFF_G,
        sc + OFF_Y, sc + OFF_ST, sc + OFF_ASUM, sc + OFF_EACS);

    // 8) cross-chunk prefix
    ssd_prefix<<<dim3(HS, 2), 256>>>(sc + OFF_ST, sc + OFF_ASUM);

    // 9) Y += exp(Acs) * (C . S_prev) + D * x
    ssd_part2<<<dim3(HS, NC, 2), 256>>>(
        sc + OFF_XBC, sc + OFF_ST, sc + OFF_EACS, D_param, sc + OFF_Y);

    // 10) gated rmsnorm -> yg hi/lo
    gate_norm_kernel<<<NTOK, 256>>>(sc + OFF_Y, sc + OFF_ZX, norm_gate, YGH, YGL);

    // 11) out = yg @ W_out.T + residual
    gemm_hf2<<<dim3(DM / BN, NTOK / BM, 1), 256, GEMM_SMEM>>>(
        YGH, YGL, WOH, out, sc + OFF_Q, NTOK, DM, DINNER, DINNER, DINNER, DM, 0, 0, 0);
}